// round 2
// baseline (speedup 1.0000x reference)
#include <cuda_runtime.h>
#include <math.h>

// Problem constants (from reference setup_inputs)
#define BB   4
#define SS   2048
#define DD   1024
#define DFF  4096
#define EE   8
#define NN   (BB*SS)          // 8192 tokens
#define KTOP 2
#define SLOTS (NN*KTOP)       // 16384
#define CAP  1280             // ceil(1.25*8192/8)
#define EPS_F 1e-9f

// ---------------- device scratch (no allocations allowed) ----------------
__device__ float g_Xbuf[EE * CAP * DD];     // dispatch buffer, reused as GEMM2 output (~42MB)
__device__ float g_H[EE * CAP * DFF];       // hidden activations (~168MB)
__device__ int   g_slot_expert[SLOTS];
__device__ int   g_slot_pos[SLOTS];         // -1 if dropped
__device__ float g_slot_p[SLOTS];           // raw softmax prob
__device__ float g_slot_w[SLOTS];           // renormalized weight
__device__ int   g_row_token[EE * CAP];     // row -> source token
__device__ int   g_cnt[EE];                 // kept rows per expert
__device__ float g_imp[EE];                 // importance sum per expert

// ---------------- 1) gating: logits, top-2, softmax ----------------
__global__ void gating_kernel(const float* __restrict__ x, const float* __restrict__ Wg)
{
    int t = blockIdx.x;
    int tid = threadIdx.x;                  // 128 threads
    const float4* xv = (const float4*)(x + (size_t)t * DD);

    float acc[EE];
#pragma unroll
    for (int e = 0; e < EE; e++) acc[e] = 0.f;

    for (int i = tid; i < DD / 4; i += 128) {
        float4 xx = xv[i];
#pragma unroll
        for (int e = 0; e < EE; e++) {
            float4 wv = *(const float4*)(Wg + (size_t)e * DD + i * 4);
            acc[e] += xx.x * wv.x + xx.y * wv.y + xx.z * wv.z + xx.w * wv.w;
        }
    }

    __shared__ float sh[EE][128];
#pragma unroll
    for (int e = 0; e < EE; e++) sh[e][tid] = acc[e];
    __syncthreads();
    for (int s = 64; s > 0; s >>= 1) {
        if (tid < s) {
#pragma unroll
            for (int e = 0; e < EE; e++) sh[e][tid] += sh[e][tid + s];
        }
        __syncthreads();
    }

    if (tid == 0) {
        float v[EE];
#pragma unroll
        for (int e = 0; e < EE; e++) v[e] = sh[e][0];
        // top-1 (earliest index on ties)
        int i0 = 0; float s0 = v[0];
#pragma unroll
        for (int e = 1; e < EE; e++) if (v[e] > s0) { s0 = v[e]; i0 = e; }
        // top-2 among e != i0
        int i1 = -1; float s1 = -INFINITY;
#pragma unroll
        for (int e = 0; e < EE; e++) if (e != i0 && v[e] > s1) { s1 = v[e]; i1 = e; }
        // softmax over [s0, s1]
        float e1 = expf(s1 - s0);
        float denom = 1.f + e1;
        float p0 = 1.f / denom;
        float p1 = e1 / denom;
        g_slot_expert[2 * t + 0] = i0;
        g_slot_expert[2 * t + 1] = i1;
        g_slot_p[2 * t + 0] = p0;
        g_slot_p[2 * t + 1] = p1;
    }
}

// ---------------- 2) ordered capacity assignment (single block) ----------------
__global__ void assign_kernel()
{
    const int T = 256;
    const int CH = SLOTS / T;               // 64 slots per thread (even -> token pairs intact)
    int tid = threadIdx.x;
    int base = tid * CH;

    __shared__ int   scnt[T][EE];
    __shared__ float simp[T][EE];

    int lc[EE];
#pragma unroll
    for (int e = 0; e < EE; e++) lc[e] = 0;
    for (int i = 0; i < CH; i++) lc[g_slot_expert[base + i]]++;
#pragma unroll
    for (int e = 0; e < EE; e++) scnt[tid][e] = lc[e];
    __syncthreads();

    if (tid < EE) {
        int e = tid, run = 0;
        for (int t2 = 0; t2 < T; t2++) { int c = scnt[t2][e]; scnt[t2][e] = run; run += c; }
        g_cnt[e] = min(run, CAP);
    }
    __syncthreads();

    int off[EE];
    float impl[EE];
#pragma unroll
    for (int e = 0; e < EE; e++) { off[e] = scnt[tid][e]; impl[e] = 0.f; }

    for (int i = 0; i < CH; i += 2) {
        int sA = base + i, sBs = base + i + 1;
        int e0 = g_slot_expert[sA], e1 = g_slot_expert[sBs];
        int p0 = off[e0]++;
        int p1 = off[e1]++;
        bool k0 = p0 < CAP, k1 = p1 < CAP;
        float w0 = k0 ? g_slot_p[sA] : 0.f;
        float w1 = k1 ? g_slot_p[sBs] : 0.f;
        float s = w0 + w1 + EPS_F;
        w0 /= s; w1 /= s;
        bool v0 = w0 > 0.f, v1 = w1 > 0.f;
        g_slot_w[sA] = w0;
        g_slot_w[sBs] = w1;
        g_slot_pos[sA]  = v0 ? p0 : -1;
        g_slot_pos[sBs] = v1 ? p1 : -1;
        int tok = (sA) >> 1;
        if (v0) { g_row_token[e0 * CAP + p0] = tok; impl[e0] += w0; }
        if (v1) { g_row_token[e1 * CAP + p1] = tok; impl[e1] += w1; }
    }
#pragma unroll
    for (int e = 0; e < EE; e++) simp[tid][e] = impl[e];
    __syncthreads();
    if (tid < EE) {
        int e = tid;
        float s = 0.f;
        for (int t2 = 0; t2 < T; t2++) s += simp[t2][e];
        g_imp[e] = s;                       // overwrite each run (graph replay safe)
    }
}

// ---------------- 3) dispatch: Xbuf[e,pos,:] = w * x[token,:] ----------------
__global__ void dispatch_kernel(const float* __restrict__ x)
{
    int slot = blockIdx.x;
    int pos = g_slot_pos[slot];
    if (pos < 0) return;
    int e = g_slot_expert[slot];
    float w = g_slot_w[slot];
    int tok = slot >> 1;
    const float4* xs = (const float4*)(x + (size_t)tok * DD);
    float4* xd = (float4*)(g_Xbuf + ((size_t)(e * CAP + pos)) * DD);
    int i = threadIdx.x;                    // 256 threads * float4 = 1024 floats
    float4 v = xs[i];
    xd[i] = make_float4(v.x * w, v.y * w, v.z * w, v.w * w);
}

// ---------------- 4/5) NT GEMM: C[m,n] = sum_k A[m,k]*B[n,k] ----------------
#define BM 128
#define BN 128
#define BK 8

template<bool RELU>
__global__ __launch_bounds__(256, 2)
void gemm_nt_kernel(const float* __restrict__ Aall, const float* __restrict__ Ball,
                    float* __restrict__ Call, int Nn, int Kk,
                    int strideA, int strideB, int strideC)
{
    int e = blockIdx.z;
    int M = g_cnt[e];
    int m0 = blockIdx.y * BM;
    if (m0 >= M) return;
    int n0 = blockIdx.x * BN;

    const float* A = Aall + (size_t)e * strideA;
    const float* B = Ball + (size_t)e * strideB;
    float*       C = Call + (size_t)e * strideC;

    __shared__ float As[BK][BM];
    __shared__ float Bs[BK][BN];

    int tid = threadIdx.x;
    int tx = tid & 15;
    int ty = tid >> 4;

    int ldRow  = tid >> 1;                  // 0..127
    int ldColV = (tid & 1) * 4;             // 0 or 4

    float acc[8][8];
#pragma unroll
    for (int i = 0; i < 8; i++)
#pragma unroll
        for (int j = 0; j < 8; j++) acc[i][j] = 0.f;

    for (int kt = 0; kt < Kk; kt += BK) {
        float4 av = make_float4(0.f, 0.f, 0.f, 0.f);
        int gm = m0 + ldRow;
        if (gm < M) av = *(const float4*)(A + (size_t)gm * Kk + kt + ldColV);
        As[ldColV + 0][ldRow] = av.x;
        As[ldColV + 1][ldRow] = av.y;
        As[ldColV + 2][ldRow] = av.z;
        As[ldColV + 3][ldRow] = av.w;

        float4 bv = *(const float4*)(B + (size_t)(n0 + ldRow) * Kk + kt + ldColV);
        Bs[ldColV + 0][ldRow] = bv.x;
        Bs[ldColV + 1][ldRow] = bv.y;
        Bs[ldColV + 2][ldRow] = bv.z;
        Bs[ldColV + 3][ldRow] = bv.w;
        __syncthreads();

#pragma unroll
        for (int kk = 0; kk < BK; kk++) {
            float4 a0 = *(const float4*)&As[kk][ty * 4];
            float4 a1 = *(const float4*)&As[kk][64 + ty * 4];
            float4 b0 = *(const float4*)&Bs[kk][tx * 4];
            float4 b1 = *(const float4*)&Bs[kk][64 + tx * 4];
            float ar[8] = {a0.x, a0.y, a0.z, a0.w, a1.x, a1.y, a1.z, a1.w};
            float br[8] = {b0.x, b0.y, b0.z, b0.w, b1.x, b1.y, b1.z, b1.w};
#pragma unroll
            for (int i = 0; i < 8; i++)
#pragma unroll
                for (int j = 0; j < 8; j++) acc[i][j] += ar[i] * br[j];
        }
        __syncthreads();
    }

#pragma unroll
    for (int i = 0; i < 8; i++) {
        int r = m0 + ((i < 4) ? (ty * 4 + i) : (64 + ty * 4 + i - 4));
        if (r < M) {
#pragma unroll
            for (int j = 0; j < 8; j++) {
                int c = n0 + ((j < 4) ? (tx * 4 + j) : (64 + tx * 4 + j - 4));
                float v = acc[i][j];
                if (RELU) v = fmaxf(v, 0.f);
                C[(size_t)r * Nn + c] = v;
            }
        }
    }
}

// ---------------- 6) combine: y[t] = sum over kept slots of Out row ----------------
__global__ void combine_kernel(float* __restrict__ y)
{
    int t = blockIdx.x;
    int i = threadIdx.x;                    // 256 threads * float4
    float4 acc = make_float4(0.f, 0.f, 0.f, 0.f);
#pragma unroll
    for (int j = 0; j < KTOP; j++) {
        int slot = t * KTOP + j;
        int pos = g_slot_pos[slot];
        if (pos >= 0) {
            int e = g_slot_expert[slot];
            const float4* o = (const float4*)(g_Xbuf + ((size_t)(e * CAP + pos)) * DD);
            float4 v = o[i];
            acc.x += v.x; acc.y += v.y; acc.z += v.z; acc.w += v.w;
        }
    }
    ((float4*)(y + (size_t)t * DD))[i] = acc;
}

// ---------------- 7) aux loss ----------------
__global__ void aux_kernel(float* __restrict__ out, int out_size)
{
    float tc = 0.f, ic = 0.f;
#pragma unroll
    for (int e = 0; e < EE; e++) { tc += (float)g_cnt[e]; ic += g_imp[e]; }
    float aux = 0.f;
#pragma unroll
    for (int e = 0; e < EE; e++) aux += ((float)g_cnt[e] / tc) * (g_imp[e] / ic);
    aux *= (float)EE;
    out[out_size - 1] = aux;
}

// ---------------- launch ----------------
extern "C" void kernel_launch(void* const* d_in, const int* in_sizes, int n_in,
                              void* d_out, int out_size)
{
    const float* x  = (const float*)d_in[0];
    const float* Wg = (const float*)d_in[1];
    const float* W1 = (const float*)d_in[2];
    const float* W2 = (const float*)d_in[3];
    float* y = (float*)d_out;
    (void)in_sizes; (void)n_in;

    // d_out is poisoned; combine writes all y, aux writes scalar, but clear padding too.
    cudaMemsetAsync(d_out, 0, (size_t)out_size * sizeof(float));

    gating_kernel<<<NN, 128>>>(x, Wg);
    assign_kernel<<<1, 256>>>();
    dispatch_kernel<<<SLOTS, 256>>>(x);

    // GEMM1: H = relu(X @ W1^T)   (per expert: M=cnt, N=DFF, K=DD)
    {
        float* Xd; cudaGetSymbolAddress((void**)&Xd, g_Xbuf);
        float* Hd; cudaGetSymbolAddress((void**)&Hd, g_H);
        dim3 grid(DFF / BN, (CAP + BM - 1) / BM, EE);
        gemm_nt_kernel<true><<<grid, 256>>>(Xd, W1, Hd, DFF, DD,
                                            CAP * DD, DFF * DD, CAP * DFF);
    }
    // GEMM2: Out = H @ W2^T   (per expert: M=cnt, N=DD, K=DFF) -> reuse g_Xbuf
    {
        float* Xd; cudaGetSymbolAddress((void**)&Xd, g_Xbuf);
        float* Hd; cudaGetSymbolAddress((void**)&Hd, g_H);
        dim3 grid(DD / BN, (CAP + BM - 1) / BM, EE);
        gemm_nt_kernel<false><<<grid, 256>>>(Hd, W2, Xd, DD, DFF,
                                             CAP * DFF, DD * DFF, CAP * DD);
    }

    combine_kernel<<<NN, 256>>>(y);
    aux_kernel<<<1, 1>>>(y, out_size);
}

// round 4
// speedup vs baseline: 1.7960x; 1.7960x over previous
#include <cuda_runtime.h>
#include <cuda_bf16.h>
#include <math.h>

// Problem constants
#define BB   4
#define SS   2048
#define DD   1024
#define DFF  4096
#define EE   8
#define NN   (BB*SS)          // 8192 tokens
#define KTOP 2
#define SLOTS (NN*KTOP)       // 16384
#define CAP  1280
#define EPS_F 1e-9f

// ---------------- device scratch (no allocations allowed) ----------------
__device__ float    g_Xbuf[EE * CAP * DD];        // GEMM2 output (fp32)
__device__ unsigned g_Xhi[EE * CAP * DD / 2];     // dispatched X, bf16x2 hi
__device__ unsigned g_Xlo[EE * CAP * DD / 2];     // bf16x2 lo
__device__ unsigned g_Hhi[EE * CAP * DFF / 2];    // hidden, bf16x2 hi
__device__ unsigned g_Hlo[EE * CAP * DFF / 2];
__device__ unsigned g_W1hi[EE * DFF * DD / 2];
__device__ unsigned g_W1lo[EE * DFF * DD / 2];
__device__ unsigned g_W2hi[EE * DD * DFF / 2];
__device__ unsigned g_W2lo[EE * DD * DFF / 2];
__device__ int   g_slot_expert[SLOTS];
__device__ int   g_slot_pos[SLOTS];
__device__ float g_slot_p[SLOTS];
__device__ float g_slot_w[SLOTS];
__device__ int   g_cnt[EE];
__device__ float g_imp[EE];

// ---------------- helpers ----------------
__device__ __forceinline__ void split2(float v0, float v1, unsigned &hi, unsigned &lo)
{
    __nv_bfloat16 h0 = __float2bfloat16(v0);
    __nv_bfloat16 h1 = __float2bfloat16(v1);
    float r0 = v0 - __bfloat162float(h0);
    float r1 = v1 - __bfloat162float(h1);
    __nv_bfloat16 l0 = __float2bfloat16(r0);
    __nv_bfloat16 l1 = __float2bfloat16(r1);
    hi = ((unsigned)__bfloat16_as_ushort(h1) << 16) | (unsigned)__bfloat16_as_ushort(h0);
    lo = ((unsigned)__bfloat16_as_ushort(l1) << 16) | (unsigned)__bfloat16_as_ushort(l0);
}

__device__ __forceinline__ void mma16816(float c[4], const unsigned a[4], const unsigned b[2])
{
    asm volatile(
        "mma.sync.aligned.m16n8k16.row.col.f32.bf16.bf16.f32 "
        "{%0,%1,%2,%3},{%4,%5,%6,%7},{%8,%9},{%0,%1,%2,%3};\n"
        : "+f"(c[0]), "+f"(c[1]), "+f"(c[2]), "+f"(c[3])
        : "r"(a[0]), "r"(a[1]), "r"(a[2]), "r"(a[3]), "r"(b[0]), "r"(b[1]));
}

__device__ __forceinline__ void cpa16(unsigned saddr, const void* g, int sz)
{
    asm volatile("cp.async.cg.shared.global [%0], [%1], 16, %2;\n"
                 :: "r"(saddr), "l"(g), "r"(sz));
}
__device__ __forceinline__ void cpa_commit() { asm volatile("cp.async.commit_group;\n"); }

// ---------------- 1) gating ----------------
__global__ void gating_kernel(const float* __restrict__ x, const float* __restrict__ Wg)
{
    int t = blockIdx.x;
    int tid = threadIdx.x;                  // 128 threads
    const float4* xv = (const float4*)(x + (size_t)t * DD);

    float acc[EE];
#pragma unroll
    for (int e = 0; e < EE; e++) acc[e] = 0.f;

    for (int i = tid; i < DD / 4; i += 128) {
        float4 xx = xv[i];
#pragma unroll
        for (int e = 0; e < EE; e++) {
            float4 wv = *(const float4*)(Wg + (size_t)e * DD + i * 4);
            acc[e] += xx.x * wv.x + xx.y * wv.y + xx.z * wv.z + xx.w * wv.w;
        }
    }

    __shared__ float sh[EE][128];
#pragma unroll
    for (int e = 0; e < EE; e++) sh[e][tid] = acc[e];
    __syncthreads();
    for (int s = 64; s > 0; s >>= 1) {
        if (tid < s) {
#pragma unroll
            for (int e = 0; e < EE; e++) sh[e][tid] += sh[e][tid + s];
        }
        __syncthreads();
    }

    if (tid == 0) {
        float v[EE];
#pragma unroll
        for (int e = 0; e < EE; e++) v[e] = sh[e][0];
        int i0 = 0; float s0 = v[0];
#pragma unroll
        for (int e = 1; e < EE; e++) if (v[e] > s0) { s0 = v[e]; i0 = e; }
        int i1 = -1; float s1 = -INFINITY;
#pragma unroll
        for (int e = 0; e < EE; e++) if (e != i0 && v[e] > s1) { s1 = v[e]; i1 = e; }
        float e1 = expf(s1 - s0);
        float denom = 1.f + e1;
        g_slot_expert[2 * t + 0] = i0;
        g_slot_expert[2 * t + 1] = i1;
        g_slot_p[2 * t + 0] = 1.f / denom;
        g_slot_p[2 * t + 1] = e1 / denom;
    }
}

// ---------------- 2) ordered capacity assignment ----------------
__global__ void assign_kernel()
{
    const int T = 256;
    const int CH = SLOTS / T;
    int tid = threadIdx.x;
    int base = tid * CH;

    __shared__ int   scnt[T][EE];
    __shared__ float simp[T][EE];

    int lc[EE];
#pragma unroll
    for (int e = 0; e < EE; e++) lc[e] = 0;
    for (int i = 0; i < CH; i++) lc[g_slot_expert[base + i]]++;
#pragma unroll
    for (int e = 0; e < EE; e++) scnt[tid][e] = lc[e];
    __syncthreads();

    if (tid < EE) {
        int e = tid, run = 0;
        for (int t2 = 0; t2 < T; t2++) { int c = scnt[t2][e]; scnt[t2][e] = run; run += c; }
        g_cnt[e] = min(run, CAP);
    }
    __syncthreads();

    int off[EE];
    float impl[EE];
#pragma unroll
    for (int e = 0; e < EE; e++) { off[e] = scnt[tid][e]; impl[e] = 0.f; }

    for (int i = 0; i < CH; i += 2) {
        int sA = base + i, sBs = base + i + 1;
        int e0 = g_slot_expert[sA], e1 = g_slot_expert[sBs];
        int p0 = off[e0]++;
        int p1 = off[e1]++;
        bool k0 = p0 < CAP, k1 = p1 < CAP;
        float w0 = k0 ? g_slot_p[sA] : 0.f;
        float w1 = k1 ? g_slot_p[sBs] : 0.f;
        float s = w0 + w1 + EPS_F;
        w0 /= s; w1 /= s;
        bool v0 = w0 > 0.f, v1 = w1 > 0.f;
        g_slot_w[sA] = w0;
        g_slot_w[sBs] = w1;
        g_slot_pos[sA]  = v0 ? p0 : -1;
        g_slot_pos[sBs] = v1 ? p1 : -1;
        if (v0) impl[e0] += w0;
        if (v1) impl[e1] += w1;
    }
#pragma unroll
    for (int e = 0; e < EE; e++) simp[tid][e] = impl[e];
    __syncthreads();
    if (tid < EE) {
        int e = tid;
        float s = 0.f;
        for (int t2 = 0; t2 < T; t2++) s += simp[t2][e];
        g_imp[e] = s;
    }
}

// ---------------- 3) dispatch: write w*x as bf16 hi/lo ----------------
__global__ void dispatch_kernel(const float* __restrict__ x)
{
    int slot = blockIdx.x;
    int pos = g_slot_pos[slot];
    if (pos < 0) return;
    int e = g_slot_expert[slot];
    float w = g_slot_w[slot];
    int tok = slot >> 1;
    const float4* xs = (const float4*)(x + (size_t)tok * DD);
    size_t rowbase = ((size_t)(e * CAP + pos)) * (DD / 2);
    int i = threadIdx.x;                    // 256 threads, 1 float4 each
    float4 v = xs[i];
    unsigned h0, l0, h1, l1;
    split2(v.x * w, v.y * w, h0, l0);
    split2(v.z * w, v.w * w, h1, l1);
    g_Xhi[rowbase + 2 * i + 0] = h0;  g_Xlo[rowbase + 2 * i + 0] = l0;
    g_Xhi[rowbase + 2 * i + 1] = h1;  g_Xlo[rowbase + 2 * i + 1] = l1;
}

// ---------------- weight split: fp32 -> bf16x2 hi/lo ----------------
__global__ void wsplit_kernel(const float* __restrict__ W,
                              unsigned* __restrict__ hi, unsigned* __restrict__ lo, int n2)
{
    int i = blockIdx.x * blockDim.x + threadIdx.x;
    int stride = gridDim.x * blockDim.x;
    for (; i < n2; i += stride) {
        float2 v = ((const float2*)W)[i];
        unsigned h, l;
        split2(v.x, v.y, h, l);
        hi[i] = h; lo[i] = l;
    }
}

// ---------------- tensor-core NT GEMM (bf16 3-split emulated fp32) ----------------
// C[m,n] = sum_k A[m,k]*B[n,k].  A/B given pre-split as packed bf16x2 along k.
// CTA tile 128x128x32, 8 warps (2x4), warp tile 64x32, mma m16n8k16.
#define PITCH 20                 // u32 pitch per row in smem (conflict-free frags)
#define STG_U32 (128 * PITCH)    // one operand array per stage: 2560 u32
#define STAGE_U32 (4 * STG_U32)  // Ahi,Alo,Bhi,Blo per stage: 10240 u32
#define GEMM_SMEM_BYTES (2 * STAGE_U32 * 4)   // 81920 B

template<bool FUSE_RELU_SPLIT>
__global__ __launch_bounds__(256, 1)
void gemm_tc_kernel(const unsigned* __restrict__ Ahi, const unsigned* __restrict__ Alo,
                    const unsigned* __restrict__ Bhi, const unsigned* __restrict__ Blo,
                    float* __restrict__ Cf, unsigned* __restrict__ Chi, unsigned* __restrict__ Clo,
                    int Nn, int Kk,
                    int strideA2, int strideB2, int strideC)
{
    extern __shared__ unsigned smem[];

    int e = blockIdx.z;
    int M = g_cnt[e];
    int m0 = blockIdx.y * 128;
    if (m0 >= M) return;
    int n0 = blockIdx.x * 128;
    int K2 = Kk >> 1;

    const unsigned* Ah = Ahi + (size_t)e * strideA2;
    const unsigned* Al = Alo + (size_t)e * strideA2;
    const unsigned* Bh = Bhi + (size_t)e * strideB2;
    const unsigned* Bl = Blo + (size_t)e * strideB2;

    int tid = threadIdx.x;
    int lane = tid & 31, warp = tid >> 5;
    int wm = warp >> 2, wn = warp & 3;      // 2 x 4 warps

    unsigned sbase = (unsigned)__cvta_generic_to_shared(smem);

    // loader mapping: 2 threads per row; each thread covers u32 [c0,c0+4) and [c0+8,c0+12)
    int lrow = tid >> 1;
    int c0 = (tid & 1) * 4;
    int gm = m0 + lrow;
    int aok = (gm < M) ? 16 : 0;
    int gmc = min(gm, M - 1);
    int gn = n0 + lrow;

    float acc[4][4][4];
#pragma unroll
    for (int mi = 0; mi < 4; mi++)
#pragma unroll
        for (int ni = 0; ni < 4; ni++)
#pragma unroll
            for (int q = 0; q < 4; q++) acc[mi][ni][q] = 0.f;

    int nstages = Kk / 32;

    // --- issue stage: per operand, two 16B copies per thread (full 16-u32 row coverage) ---
    auto issue = [&](int it, int st) {
        int kt2 = it * 16;
        unsigned dst = sbase + (unsigned)(st * STAGE_U32 + lrow * PITCH + c0) * 4;
        size_t ga = (size_t)gmc * K2 + kt2 + c0;
        size_t gb = (size_t)gn  * K2 + kt2 + c0;
        cpa16(dst,                          Ah + ga,     aok);
        cpa16(dst + 32,                     Ah + ga + 8, aok);
        cpa16(dst + STG_U32 * 4,            Al + ga,     aok);
        cpa16(dst + STG_U32 * 4 + 32,       Al + ga + 8, aok);
        cpa16(dst + 2 * STG_U32 * 4,        Bh + gb,     16);
        cpa16(dst + 2 * STG_U32 * 4 + 32,   Bh + gb + 8, 16);
        cpa16(dst + 3 * STG_U32 * 4,        Bl + gb,     16);
        cpa16(dst + 3 * STG_U32 * 4 + 32,   Bl + gb + 8, 16);
        cpa_commit();
    };

    issue(0, 0);

    for (int it = 0; it < nstages; it++) {
        if (it + 1 < nstages) {
            issue(it + 1, (it + 1) & 1);
            asm volatile("cp.async.wait_group 1;\n");
        } else {
            asm volatile("cp.async.wait_group 0;\n");
        }
        __syncthreads();

        const unsigned* sAh = smem + (it & 1) * STAGE_U32;
        const unsigned* sAl = sAh + STG_U32;
        const unsigned* sBh = sAh + 2 * STG_U32;
        const unsigned* sBl = sAh + 3 * STG_U32;

#pragma unroll
        for (int ks = 0; ks < 2; ks++) {
            int k2b = ks * 8 + (lane & 3);
            unsigned ah[4][4], al[4][4];
#pragma unroll
            for (int mi = 0; mi < 4; mi++) {
                int r = wm * 64 + mi * 16 + (lane >> 2);
                ah[mi][0] = sAh[r * PITCH + k2b];
                ah[mi][1] = sAh[(r + 8) * PITCH + k2b];
                ah[mi][2] = sAh[r * PITCH + k2b + 4];
                ah[mi][3] = sAh[(r + 8) * PITCH + k2b + 4];
                al[mi][0] = sAl[r * PITCH + k2b];
                al[mi][1] = sAl[(r + 8) * PITCH + k2b];
                al[mi][2] = sAl[r * PITCH + k2b + 4];
                al[mi][3] = sAl[(r + 8) * PITCH + k2b + 4];
            }
            unsigned bh[4][2], bl[4][2];
#pragma unroll
            for (int ni = 0; ni < 4; ni++) {
                int c = wn * 32 + ni * 8 + (lane >> 2);
                bh[ni][0] = sBh[c * PITCH + k2b];
                bh[ni][1] = sBh[c * PITCH + k2b + 4];
                bl[ni][0] = sBl[c * PITCH + k2b];
                bl[ni][1] = sBl[c * PITCH + k2b + 4];
            }
#pragma unroll
            for (int mi = 0; mi < 4; mi++)
#pragma unroll
                for (int ni = 0; ni < 4; ni++) {
                    mma16816(acc[mi][ni], ah[mi], bh[ni]);
                    mma16816(acc[mi][ni], ah[mi], bl[ni]);
                    mma16816(acc[mi][ni], al[mi], bh[ni]);
                }
        }
        __syncthreads();
    }

    // --- epilogue ---
#pragma unroll
    for (int mi = 0; mi < 4; mi++) {
#pragma unroll
        for (int ni = 0; ni < 4; ni++) {
            int r0 = m0 + wm * 64 + mi * 16 + (lane >> 2);
            int cc = n0 + wn * 32 + ni * 8 + 2 * (lane & 3);
            float* a = acc[mi][ni];
            if (FUSE_RELU_SPLIT) {
                size_t eoff = (size_t)e * ((size_t)CAP * (Nn >> 1));
                if (r0 < M) {
                    unsigned h, l;
                    split2(fmaxf(a[0], 0.f), fmaxf(a[1], 0.f), h, l);
                    size_t idx = eoff + (size_t)r0 * (Nn >> 1) + (cc >> 1);
                    Chi[idx] = h; Clo[idx] = l;
                }
                if (r0 + 8 < M) {
                    unsigned h, l;
                    split2(fmaxf(a[2], 0.f), fmaxf(a[3], 0.f), h, l);
                    size_t idx = eoff + (size_t)(r0 + 8) * (Nn >> 1) + (cc >> 1);
                    Chi[idx] = h; Clo[idx] = l;
                }
            } else {
                size_t eoff = (size_t)e * strideC;
                if (r0 < M)
                    *(float2*)(Cf + eoff + (size_t)r0 * Nn + cc) = make_float2(a[0], a[1]);
                if (r0 + 8 < M)
                    *(float2*)(Cf + eoff + (size_t)(r0 + 8) * Nn + cc) = make_float2(a[2], a[3]);
            }
        }
    }
}

// ---------------- 6) combine ----------------
__global__ void combine_kernel(float* __restrict__ y)
{
    int t = blockIdx.x;
    int i = threadIdx.x;
    float4 acc = make_float4(0.f, 0.f, 0.f, 0.f);
#pragma unroll
    for (int j = 0; j < KTOP; j++) {
        int slot = t * KTOP + j;
        int pos = g_slot_pos[slot];
        if (pos >= 0) {
            int e = g_slot_expert[slot];
            const float4* o = (const float4*)(g_Xbuf + ((size_t)(e * CAP + pos)) * DD);
            float4 v = o[i];
            acc.x += v.x; acc.y += v.y; acc.z += v.z; acc.w += v.w;
        }
    }
    ((float4*)(y + (size_t)t * DD))[i] = acc;
}

// ---------------- 7) aux loss ----------------
__global__ void aux_kernel(float* __restrict__ out, int out_size)
{
    float tc = 0.f, ic = 0.f;
#pragma unroll
    for (int e = 0; e < EE; e++) { tc += (float)g_cnt[e]; ic += g_imp[e]; }
    float aux = 0.f;
#pragma unroll
    for (int e = 0; e < EE; e++) aux += ((float)g_cnt[e] / tc) * (g_imp[e] / ic);
    out[out_size - 1] = aux * (float)EE;
}

// ---------------- launch ----------------
extern "C" void kernel_launch(void* const* d_in, const int* in_sizes, int n_in,
                              void* d_out, int out_size)
{
    const float* x  = (const float*)d_in[0];
    const float* Wg = (const float*)d_in[1];
    const float* W1 = (const float*)d_in[2];
    const float* W2 = (const float*)d_in[3];
    float* y = (float*)d_out;
    (void)in_sizes; (void)n_in;

    cudaFuncSetAttribute(gemm_tc_kernel<true>,  cudaFuncAttributeMaxDynamicSharedMemorySize, GEMM_SMEM_BYTES);
    cudaFuncSetAttribute(gemm_tc_kernel<false>, cudaFuncAttributeMaxDynamicSharedMemorySize, GEMM_SMEM_BYTES);

    cudaMemsetAsync(d_out, 0, (size_t)out_size * sizeof(float));

    gating_kernel<<<NN, 128>>>(x, Wg);
    assign_kernel<<<1, 256>>>();
    dispatch_kernel<<<SLOTS, 256>>>(x);

    unsigned *Xhi, *Xlo, *Hhi, *Hlo, *W1hi, *W1lo, *W2hi, *W2lo;
    float *Xbuf;
    cudaGetSymbolAddress((void**)&Xhi,  g_Xhi);
    cudaGetSymbolAddress((void**)&Xlo,  g_Xlo);
    cudaGetSymbolAddress((void**)&Hhi,  g_Hhi);
    cudaGetSymbolAddress((void**)&Hlo,  g_Hlo);
    cudaGetSymbolAddress((void**)&W1hi, g_W1hi);
    cudaGetSymbolAddress((void**)&W1lo, g_W1lo);
    cudaGetSymbolAddress((void**)&W2hi, g_W2hi);
    cudaGetSymbolAddress((void**)&W2lo, g_W2lo);
    cudaGetSymbolAddress((void**)&Xbuf, g_Xbuf);

    wsplit_kernel<<<2048, 256>>>(W1, W1hi, W1lo, EE * DFF * DD / 2);
    wsplit_kernel<<<2048, 256>>>(W2, W2hi, W2lo, EE * DD * DFF / 2);

    // GEMM1: H = relu(X @ W1^T), per expert M=cnt, N=DFF, K=DD; fused bf16-split output
    {
        dim3 grid(DFF / 128, (CAP + 127) / 128, EE);
        gemm_tc_kernel<true><<<grid, 256, GEMM_SMEM_BYTES>>>(
            Xhi, Xlo, W1hi, W1lo, nullptr, Hhi, Hlo,
            DFF, DD, CAP * DD / 2, DFF * DD / 2, 0);
    }
    // GEMM2: Out = H @ W2^T, per expert M=cnt, N=DD, K=DFF; fp32 output
    {
        dim3 grid(DD / 128, (CAP + 127) / 128, EE);
        gemm_tc_kernel<false><<<grid, 256, GEMM_SMEM_BYTES>>>(
            Hhi, Hlo, W2hi, W2lo, Xbuf, nullptr, nullptr,
            DD, DFF, CAP * DFF / 2, DD * DFF / 2, CAP * DD);
    }

    combine_kernel<<<NN, 256>>>(y);
    aux_kernel<<<1, 1>>>(y, out_size);
}

// round 7
// speedup vs baseline: 1.8062x; 1.0057x over previous
#include <cuda_runtime.h>
#include <cuda_bf16.h>
#include <stdint.h>
#include <math.h>

// Problem constants
#define BB   4
#define SS   2048
#define DD   1024
#define DFF  4096
#define EE   8
#define NN   (BB*SS)          // 8192 tokens
#define KTOP 2
#define SLOTS (NN*KTOP)       // 16384
#define CAP  1280
#define EPS_F 1e-9f

// ---------------- device scratch ----------------
__device__ float    g_Xbuf[EE * CAP * DD];        // GEMM2 output (fp32)
__device__ unsigned g_Xhi[EE * CAP * DD / 2];     // dispatched X, bf16x2 hi
__device__ unsigned g_Xlo[EE * CAP * DD / 2];
__device__ unsigned g_Hhi[EE * CAP * DFF / 2];    // hidden, bf16x2 hi
__device__ unsigned g_Hlo[EE * CAP * DFF / 2];
__device__ unsigned g_W1hi[EE * DFF * DD / 2];
__device__ unsigned g_W1lo[EE * DFF * DD / 2];
__device__ unsigned g_W2hi[EE * DD * DFF / 2];
__device__ unsigned g_W2lo[EE * DD * DFF / 2];
__device__ int   g_slot_expert[SLOTS];
__device__ int   g_slot_pos[SLOTS];
__device__ float g_slot_p[SLOTS];
__device__ float g_slot_w[SLOTS];
__device__ int   g_cnt[EE];
__device__ float g_imp[EE];

// ---------------- helpers ----------------
__device__ __forceinline__ void split2(float v0, float v1, unsigned &hi, unsigned &lo)
{
    __nv_bfloat16 h0 = __float2bfloat16(v0);
    __nv_bfloat16 h1 = __float2bfloat16(v1);
    float r0 = v0 - __bfloat162float(h0);
    float r1 = v1 - __bfloat162float(h1);
    __nv_bfloat16 l0 = __float2bfloat16(r0);
    __nv_bfloat16 l1 = __float2bfloat16(r1);
    hi = ((unsigned)__bfloat16_as_ushort(h1) << 16) | (unsigned)__bfloat16_as_ushort(h0);
    lo = ((unsigned)__bfloat16_as_ushort(l1) << 16) | (unsigned)__bfloat16_as_ushort(l0);
}

__device__ __forceinline__ void mma16816(float c[4], const uint32_t a[4], const uint32_t b[2])
{
    asm volatile(
        "mma.sync.aligned.m16n8k16.row.col.f32.bf16.bf16.f32 "
        "{%0,%1,%2,%3},{%4,%5,%6,%7},{%8,%9},{%0,%1,%2,%3};\n"
        : "+f"(c[0]), "+f"(c[1]), "+f"(c[2]), "+f"(c[3])
        : "r"(a[0]), "r"(a[1]), "r"(a[2]), "r"(a[3]), "r"(b[0]), "r"(b[1]));
}

__device__ __forceinline__ void ldsm4(uint32_t r[4], uint32_t saddr)
{
    asm volatile("ldmatrix.sync.aligned.m8n8.x4.shared.b16 {%0,%1,%2,%3}, [%4];"
                 : "=r"(r[0]), "=r"(r[1]), "=r"(r[2]), "=r"(r[3]) : "r"(saddr));
}

__device__ __forceinline__ void cpa16(uint32_t saddr, const void* g)
{
    asm volatile("cp.async.cg.shared.global [%0], [%1], 16;\n" :: "r"(saddr), "l"(g));
}
__device__ __forceinline__ void cpa_commit() { asm volatile("cp.async.commit_group;\n"); }

__device__ __forceinline__ uint32_t smem_u32(const void* p) {
    uint32_t a;
    asm("{ .reg .u64 t; cvta.to.shared.u64 t, %1; cvt.u32.u64 %0, t; }" : "=r"(a) : "l"(p));
    return a;
}

// ---------------- 1) gating ----------------
__global__ void gating_kernel(const float* __restrict__ x, const float* __restrict__ Wg)
{
    int t = blockIdx.x;
    int tid = threadIdx.x;                  // 128 threads
    const float4* xv = (const float4*)(x + (size_t)t * DD);

    float acc[EE];
#pragma unroll
    for (int e = 0; e < EE; e++) acc[e] = 0.f;

    for (int i = tid; i < DD / 4; i += 128) {
        float4 xx = xv[i];
#pragma unroll
        for (int e = 0; e < EE; e++) {
            float4 wv = *(const float4*)(Wg + (size_t)e * DD + i * 4);
            acc[e] += xx.x * wv.x + xx.y * wv.y + xx.z * wv.z + xx.w * wv.w;
        }
    }

    __shared__ float sh[EE][128];
#pragma unroll
    for (int e = 0; e < EE; e++) sh[e][tid] = acc[e];
    __syncthreads();
    for (int s = 64; s > 0; s >>= 1) {
        if (tid < s) {
#pragma unroll
            for (int e = 0; e < EE; e++) sh[e][tid] += sh[e][tid + s];
        }
        __syncthreads();
    }

    if (tid == 0) {
        float v[EE];
#pragma unroll
        for (int e = 0; e < EE; e++) v[e] = sh[e][0];
        int i0 = 0; float s0 = v[0];
#pragma unroll
        for (int e = 1; e < EE; e++) if (v[e] > s0) { s0 = v[e]; i0 = e; }
        int i1 = -1; float s1 = -INFINITY;
#pragma unroll
        for (int e = 0; e < EE; e++) if (e != i0 && v[e] > s1) { s1 = v[e]; i1 = e; }
        float e1 = expf(s1 - s0);
        float denom = 1.f + e1;
        g_slot_expert[2 * t + 0] = i0;
        g_slot_expert[2 * t + 1] = i1;
        g_slot_p[2 * t + 0] = 1.f / denom;
        g_slot_p[2 * t + 1] = e1 / denom;
    }
}

// ---------------- 2) ordered capacity assignment ----------------
__global__ void assign_kernel()
{
    const int T = 256;
    const int CH = SLOTS / T;
    int tid = threadIdx.x;
    int base = tid * CH;

    __shared__ int   scnt[T][EE];
    __shared__ float simp[T][EE];

    int lc[EE];
#pragma unroll
    for (int e = 0; e < EE; e++) lc[e] = 0;
    for (int i = 0; i < CH; i++) lc[g_slot_expert[base + i]]++;
#pragma unroll
    for (int e = 0; e < EE; e++) scnt[tid][e] = lc[e];
    __syncthreads();

    if (tid < EE) {
        int e = tid, run = 0;
        for (int t2 = 0; t2 < T; t2++) { int c = scnt[t2][e]; scnt[t2][e] = run; run += c; }
        g_cnt[e] = min(run, CAP);
    }
    __syncthreads();

    int off[EE];
    float impl[EE];
#pragma unroll
    for (int e = 0; e < EE; e++) { off[e] = scnt[tid][e]; impl[e] = 0.f; }

    for (int i = 0; i < CH; i += 2) {
        int sA = base + i, sBs = base + i + 1;
        int e0 = g_slot_expert[sA], e1 = g_slot_expert[sBs];
        int p0 = off[e0]++;
        int p1 = off[e1]++;
        bool k0 = p0 < CAP, k1 = p1 < CAP;
        float w0 = k0 ? g_slot_p[sA] : 0.f;
        float w1 = k1 ? g_slot_p[sBs] : 0.f;
        float s = w0 + w1 + EPS_F;
        w0 /= s; w1 /= s;
        bool v0 = w0 > 0.f, v1 = w1 > 0.f;
        g_slot_w[sA] = w0;
        g_slot_w[sBs] = w1;
        g_slot_pos[sA]  = v0 ? p0 : -1;
        g_slot_pos[sBs] = v1 ? p1 : -1;
        if (v0) impl[e0] += w0;
        if (v1) impl[e1] += w1;
    }
#pragma unroll
    for (int e = 0; e < EE; e++) simp[tid][e] = impl[e];
    __syncthreads();
    if (tid < EE) {
        int e = tid;
        float s = 0.f;
        for (int t2 = 0; t2 < T; t2++) s += simp[t2][e];
        g_imp[e] = s;
    }
}

// ---------------- 3) dispatch ----------------
__global__ void dispatch_kernel(const float* __restrict__ x)
{
    int slot = blockIdx.x;
    int pos = g_slot_pos[slot];
    if (pos < 0) return;
    int e = g_slot_expert[slot];
    float w = g_slot_w[slot];
    int tok = slot >> 1;
    const float4* xs = (const float4*)(x + (size_t)tok * DD);
    size_t rowbase = ((size_t)(e * CAP + pos)) * (DD / 2);
    int i = threadIdx.x;                    // 256 threads
    float4 v = xs[i];
    unsigned h0, l0, h1, l1;
    split2(v.x * w, v.y * w, h0, l0);
    split2(v.z * w, v.w * w, h1, l1);
    g_Xhi[rowbase + 2 * i + 0] = h0;  g_Xlo[rowbase + 2 * i + 0] = l0;
    g_Xhi[rowbase + 2 * i + 1] = h1;  g_Xlo[rowbase + 2 * i + 1] = l1;
}

// ---------------- weight split ----------------
__global__ void wsplit_kernel(const float* __restrict__ W,
                              unsigned* __restrict__ hi, unsigned* __restrict__ lo, int n2)
{
    int i = blockIdx.x * blockDim.x + threadIdx.x;
    int stride = gridDim.x * blockDim.x;
    for (; i < n2; i += stride) {
        float2 v = ((const float2*)W)[i];
        unsigned h, l;
        split2(v.x, v.y, h, l);
        hi[i] = h; lo[i] = l;
    }
}

// ---------------- ldmatrix + mma.sync NT GEMM (bf16 3-split) ----------------
// C[m,n] = sum_k A[m,k]*B[n,k].  CTA tile 128x128x32, 8 warps (2x4), warp 64x32.
// 3-stage cp.async ring, one __syncthreads per stage.
#define PITCH 20                   // u32 per 32-bf16 row (16 data + 4 pad); LDSM conflict-free
#define OP_U32 (128 * PITCH)       // one operand per stage: 2560 u32
#define STAGE_U32 (4 * OP_U32)     // Ah, Al, Bh, Bl: 10240 u32 (40 KB)
#define NSTAGE 3
#define GEMM_SMEM_BYTES (NSTAGE * STAGE_U32 * 4)   // 122880 B
static_assert(GEMM_SMEM_BYTES <= 227 * 1024, "smem");

template<bool FUSE_RELU_SPLIT>
__global__ __launch_bounds__(256, 1)
void gemm_tc_kernel(const unsigned* __restrict__ Ahi, const unsigned* __restrict__ Alo,
                    const unsigned* __restrict__ Bhi, const unsigned* __restrict__ Blo,
                    float* __restrict__ Cf, unsigned* __restrict__ Chi, unsigned* __restrict__ Clo,
                    int Nn, int Kk,
                    int strideA2, int strideB2, int strideC)
{
    extern __shared__ unsigned smem[];

    int e = blockIdx.z;
    int M = g_cnt[e];
    int m0 = blockIdx.y * 128;
    if (m0 >= M) return;
    int n0 = blockIdx.x * 128;
    int K2 = Kk >> 1;

    const unsigned* Ah = Ahi + (size_t)e * strideA2;
    const unsigned* Al = Alo + (size_t)e * strideA2;
    const unsigned* Bh = Bhi + (size_t)e * strideB2;
    const unsigned* Bl = Blo + (size_t)e * strideB2;

    int tid = threadIdx.x;
    int lane = tid & 31, warp = tid >> 5;
    int wm = warp >> 2, wn = warp & 3;      // 2 x 4 warps

    uint32_t sbase = smem_u32(smem);

    // loader mapping: 2 threads/row; thread covers u32 [c0,c0+4) and [c0+8,c0+12)
    int lrow = tid >> 1;
    int c0 = (tid & 1) * 4;
    int gm = m0 + lrow;
    int gmc = min(gm, M - 1);
    int gn = n0 + lrow;

    // LDSM per-lane geometry
    int aRow  = wm * 64 + (lane & 15);            // + mi*16
    int aHalf = lane >> 4;                        // k-half 0/1
    int bRow  = wn * 32 + (lane & 7) + ((lane >> 4) << 3);  // + ni2*16
    int bHalf = (lane >> 3) & 1;

    float acc[4][4][4];
#pragma unroll
    for (int mi = 0; mi < 4; mi++)
#pragma unroll
        for (int ni = 0; ni < 4; ni++)
#pragma unroll
            for (int q = 0; q < 4; q++) acc[mi][ni][q] = 0.f;

    int nch = Kk / 32;

    auto issue = [&](int it) {
        uint32_t soff = (uint32_t)(it % NSTAGE) * STAGE_U32;
        int kt2 = it * 16;
        uint32_t dst = sbase + (uint32_t)(soff + lrow * PITCH + c0) * 4;
        size_t ga = (size_t)gmc * K2 + kt2 + c0;
        size_t gb = (size_t)gn  * K2 + kt2 + c0;
        cpa16(dst,                       Ah + ga);
        cpa16(dst + 32,                  Ah + ga + 8);
        cpa16(dst + OP_U32 * 4,          Al + ga);
        cpa16(dst + OP_U32 * 4 + 32,     Al + ga + 8);
        cpa16(dst + 2 * OP_U32 * 4,      Bh + gb);
        cpa16(dst + 2 * OP_U32 * 4 + 32, Bh + gb + 8);
        cpa16(dst + 3 * OP_U32 * 4,      Bl + gb);
        cpa16(dst + 3 * OP_U32 * 4 + 32, Bl + gb + 8);
        cpa_commit();
    };

    issue(0);
    issue(1);

    for (int it = 0; it < nch; it++) {
        if (it + 1 < nch) asm volatile("cp.async.wait_group 1;\n" ::: "memory");
        else              asm volatile("cp.async.wait_group 0;\n" ::: "memory");
        __syncthreads();

        if (it + 2 < nch) issue(it + 2);     // refills buffer (it-1)%3, freed by the sync

        uint32_t sA_h = sbase + (uint32_t)((it % NSTAGE) * STAGE_U32) * 4;
        uint32_t sA_l = sA_h + OP_U32 * 4;
        uint32_t sB_h = sA_h + 2 * OP_U32 * 4;
        uint32_t sB_l = sA_h + 3 * OP_U32 * 4;

#pragma unroll
        for (int ks = 0; ks < 2; ks++) {
            int kb = ks * 8;
            uint32_t bh[2][4], bl[2][4];
#pragma unroll
            for (int n2 = 0; n2 < 2; n2++) {
                uint32_t ao = (uint32_t)((bRow + n2 * 16) * PITCH + kb + bHalf * 4) * 4;
                ldsm4(bh[n2], sB_h + ao);
                ldsm4(bl[n2], sB_l + ao);
            }
#pragma unroll
            for (int mi = 0; mi < 4; mi++) {
                uint32_t ah[4], al[4];
                uint32_t ao = (uint32_t)((aRow + mi * 16) * PITCH + kb + aHalf * 4) * 4;
                ldsm4(ah, sA_h + ao);
                ldsm4(al, sA_l + ao);
#pragma unroll
                for (int ni = 0; ni < 4; ni++) {
                    const uint32_t* bph = &bh[ni >> 1][(ni & 1) * 2];
                    const uint32_t* bpl = &bl[ni >> 1][(ni & 1) * 2];
                    mma16816(acc[mi][ni], ah, bph);
                    mma16816(acc[mi][ni], ah, bpl);
                    mma16816(acc[mi][ni], al, bph);
                }
            }
        }
        __syncthreads();   // all warps done with buffer `it` before it is refilled
    }

    // --- epilogue ---
#pragma unroll
    for (int mi = 0; mi < 4; mi++) {
#pragma unroll
        for (int ni = 0; ni < 4; ni++) {
            int r0 = m0 + wm * 64 + mi * 16 + (lane >> 2);
            int cc = n0 + wn * 32 + ni * 8 + 2 * (lane & 3);
            float* a = acc[mi][ni];
            if (FUSE_RELU_SPLIT) {
                size_t eoff = (size_t)e * ((size_t)CAP * (Nn >> 1));
                if (r0 < M) {
                    unsigned h, l;
                    split2(fmaxf(a[0], 0.f), fmaxf(a[1], 0.f), h, l);
                    size_t idx = eoff + (size_t)r0 * (Nn >> 1) + (cc >> 1);
                    Chi[idx] = h; Clo[idx] = l;
                }
                if (r0 + 8 < M) {
                    unsigned h, l;
                    split2(fmaxf(a[2], 0.f), fmaxf(a[3], 0.f), h, l);
                    size_t idx = eoff + (size_t)(r0 + 8) * (Nn >> 1) + (cc >> 1);
                    Chi[idx] = h; Clo[idx] = l;
                }
            } else {
                size_t eoff = (size_t)e * strideC;
                if (r0 < M)
                    *(float2*)(Cf + eoff + (size_t)r0 * Nn + cc) = make_float2(a[0], a[1]);
                if (r0 + 8 < M)
                    *(float2*)(Cf + eoff + (size_t)(r0 + 8) * Nn + cc) = make_float2(a[2], a[3]);
            }
        }
    }
}

// ---------------- 6) combine ----------------
__global__ void combine_kernel(float* __restrict__ y)
{
    int t = blockIdx.x;
    int i = threadIdx.x;
    float4 acc = make_float4(0.f, 0.f, 0.f, 0.f);
#pragma unroll
    for (int j = 0; j < KTOP; j++) {
        int slot = t * KTOP + j;
        int pos = g_slot_pos[slot];
        if (pos >= 0) {
            int e = g_slot_expert[slot];
            const float4* o = (const float4*)(g_Xbuf + ((size_t)(e * CAP + pos)) * DD);
            float4 v = o[i];
            acc.x += v.x; acc.y += v.y; acc.z += v.z; acc.w += v.w;
        }
    }
    ((float4*)(y + (size_t)t * DD))[i] = acc;
}

// ---------------- 7) aux loss ----------------
__global__ void aux_kernel(float* __restrict__ out, int out_size)
{
    float tc = 0.f, ic = 0.f;
#pragma unroll
    for (int e = 0; e < EE; e++) { tc += (float)g_cnt[e]; ic += g_imp[e]; }
    float aux = 0.f;
#pragma unroll
    for (int e = 0; e < EE; e++) aux += ((float)g_cnt[e] / tc) * (g_imp[e] / ic);
    out[out_size - 1] = aux * (float)EE;
}

// ---------------- launch ----------------
extern "C" void kernel_launch(void* const* d_in, const int* in_sizes, int n_in,
                              void* d_out, int out_size)
{
    const float* x  = (const float*)d_in[0];
    const float* Wg = (const float*)d_in[1];
    const float* W1 = (const float*)d_in[2];
    const float* W2 = (const float*)d_in[3];
    float* y = (float*)d_out;
    (void)in_sizes; (void)n_in;

    cudaFuncSetAttribute(gemm_tc_kernel<true>,  cudaFuncAttributeMaxDynamicSharedMemorySize, GEMM_SMEM_BYTES);
    cudaFuncSetAttribute(gemm_tc_kernel<false>, cudaFuncAttributeMaxDynamicSharedMemorySize, GEMM_SMEM_BYTES);

    cudaMemsetAsync(d_out, 0, (size_t)out_size * sizeof(float));

    gating_kernel<<<NN, 128>>>(x, Wg);
    assign_kernel<<<1, 256>>>();
    dispatch_kernel<<<SLOTS, 256>>>(x);

    unsigned *Xhi, *Xlo, *Hhi, *Hlo, *W1hi, *W1lo, *W2hi, *W2lo;
    float *Xbuf;
    cudaGetSymbolAddress((void**)&Xhi,  g_Xhi);
    cudaGetSymbolAddress((void**)&Xlo,  g_Xlo);
    cudaGetSymbolAddress((void**)&Hhi,  g_Hhi);
    cudaGetSymbolAddress((void**)&Hlo,  g_Hlo);
    cudaGetSymbolAddress((void**)&W1hi, g_W1hi);
    cudaGetSymbolAddress((void**)&W1lo, g_W1lo);
    cudaGetSymbolAddress((void**)&W2hi, g_W2hi);
    cudaGetSymbolAddress((void**)&W2lo, g_W2lo);
    cudaGetSymbolAddress((void**)&Xbuf, g_Xbuf);

    wsplit_kernel<<<2048, 256>>>(W1, W1hi, W1lo, EE * DFF * DD / 2);
    wsplit_kernel<<<2048, 256>>>(W2, W2hi, W2lo, EE * DD * DFF / 2);

    // GEMM1: H = relu(X @ W1^T); per expert M=cnt, N=DFF, K=DD; fused relu+split output
    {
        dim3 grid(DFF / 128, (CAP + 127) / 128, EE);
        gemm_tc_kernel<true><<<grid, 256, GEMM_SMEM_BYTES>>>(
            Xhi, Xlo, W1hi, W1lo, nullptr, Hhi, Hlo,
            DFF, DD, CAP * DD / 2, DFF * DD / 2, 0);
    }
    // GEMM2: Out = H @ W2^T; per expert M=cnt, N=DD, K=DFF; fp32 output
    {
        dim3 grid(DD / 128, (CAP + 127) / 128, EE);
        gemm_tc_kernel<false><<<grid, 256, GEMM_SMEM_BYTES>>>(
            Hhi, Hlo, W2hi, W2lo, Xbuf, nullptr, nullptr,
            DD, DFF, CAP * DFF / 2, DD * DFF / 2, CAP * DD);
    }

    combine_kernel<<<NN, 256>>>(y);
    aux_kernel<<<1, 1>>>(y, out_size);
}

// round 8
// speedup vs baseline: 2.1913x; 1.2132x over previous
#include <cuda_runtime.h>
#include <cuda_bf16.h>
#include <stdint.h>
#include <math.h>

// Problem constants
#define BB   4
#define SS   2048
#define DD   1024
#define DFF  4096
#define EE   8
#define NN   (BB*SS)          // 8192 tokens
#define KTOP 2
#define SLOTS (NN*KTOP)       // 16384
#define CAP  1280
#define EPS_F 1e-9f

// ---------------- device scratch ----------------
__device__ float    g_Xbuf[EE * CAP * DD];        // GEMM2 output (fp32)
__device__ unsigned g_Xhi[EE * CAP * DD / 2];     // dispatched X, bf16x2 hi
__device__ unsigned g_Xlo[EE * CAP * DD / 2];
__device__ unsigned g_Hhi[EE * CAP * DFF / 2];    // hidden, bf16x2 hi
__device__ unsigned g_Hlo[EE * CAP * DFF / 2];
__device__ unsigned g_W1hi[EE * DFF * DD / 2];
__device__ unsigned g_W1lo[EE * DFF * DD / 2];
__device__ unsigned g_W2hi[EE * DD * DFF / 2];
__device__ unsigned g_W2lo[EE * DD * DFF / 2];
__device__ int   g_slot_expert[SLOTS];
__device__ int   g_slot_pos[SLOTS];
__device__ float g_slot_p[SLOTS];
__device__ float g_slot_w[SLOTS];
__device__ int   g_cnt[EE];
__device__ float g_imp[EE];

// ---------------- helpers ----------------
__device__ __forceinline__ void split2(float v0, float v1, unsigned &hi, unsigned &lo)
{
    __nv_bfloat16 h0 = __float2bfloat16(v0);
    __nv_bfloat16 h1 = __float2bfloat16(v1);
    float r0 = v0 - __bfloat162float(h0);
    float r1 = v1 - __bfloat162float(h1);
    __nv_bfloat16 l0 = __float2bfloat16(r0);
    __nv_bfloat16 l1 = __float2bfloat16(r1);
    hi = ((unsigned)__bfloat16_as_ushort(h1) << 16) | (unsigned)__bfloat16_as_ushort(h0);
    lo = ((unsigned)__bfloat16_as_ushort(l1) << 16) | (unsigned)__bfloat16_as_ushort(l0);
}

__device__ __forceinline__ void mma16816(float c[4], const uint32_t a[4], const uint32_t b[2])
{
    asm volatile(
        "mma.sync.aligned.m16n8k16.row.col.f32.bf16.bf16.f32 "
        "{%0,%1,%2,%3},{%4,%5,%6,%7},{%8,%9},{%0,%1,%2,%3};\n"
        : "+f"(c[0]), "+f"(c[1]), "+f"(c[2]), "+f"(c[3])
        : "r"(a[0]), "r"(a[1]), "r"(a[2]), "r"(a[3]), "r"(b[0]), "r"(b[1]));
}

__device__ __forceinline__ void ldsm4(uint32_t r[4], uint32_t saddr)
{
    asm volatile("ldmatrix.sync.aligned.m8n8.x4.shared.b16 {%0,%1,%2,%3}, [%4];"
                 : "=r"(r[0]), "=r"(r[1]), "=r"(r[2]), "=r"(r[3]) : "r"(saddr));
}

__device__ __forceinline__ void cpa16(uint32_t saddr, const void* g)
{
    asm volatile("cp.async.cg.shared.global [%0], [%1], 16;\n" :: "r"(saddr), "l"(g));
}
__device__ __forceinline__ void cpa_commit() { asm volatile("cp.async.commit_group;\n"); }

__device__ __forceinline__ uint32_t smem_u32(const void* p) {
    uint32_t a;
    asm("{ .reg .u64 t; cvta.to.shared.u64 t, %1; cvt.u32.u64 %0, t; }" : "=r"(a) : "l"(p));
    return a;
}

// ---------------- 1) gating ----------------
__global__ void gating_kernel(const float* __restrict__ x, const float* __restrict__ Wg)
{
    int t = blockIdx.x;
    int tid = threadIdx.x;                  // 128 threads
    const float4* xv = (const float4*)(x + (size_t)t * DD);

    float acc[EE];
#pragma unroll
    for (int e = 0; e < EE; e++) acc[e] = 0.f;

    for (int i = tid; i < DD / 4; i += 128) {
        float4 xx = xv[i];
#pragma unroll
        for (int e = 0; e < EE; e++) {
            float4 wv = *(const float4*)(Wg + (size_t)e * DD + i * 4);
            acc[e] += xx.x * wv.x + xx.y * wv.y + xx.z * wv.z + xx.w * wv.w;
        }
    }

    __shared__ float sh[EE][128];
#pragma unroll
    for (int e = 0; e < EE; e++) sh[e][tid] = acc[e];
    __syncthreads();
    for (int s = 64; s > 0; s >>= 1) {
        if (tid < s) {
#pragma unroll
            for (int e = 0; e < EE; e++) sh[e][tid] += sh[e][tid + s];
        }
        __syncthreads();
    }

    if (tid == 0) {
        float v[EE];
#pragma unroll
        for (int e = 0; e < EE; e++) v[e] = sh[e][0];
        int i0 = 0; float s0 = v[0];
#pragma unroll
        for (int e = 1; e < EE; e++) if (v[e] > s0) { s0 = v[e]; i0 = e; }
        int i1 = -1; float s1 = -INFINITY;
#pragma unroll
        for (int e = 0; e < EE; e++) if (e != i0 && v[e] > s1) { s1 = v[e]; i1 = e; }
        float e1 = expf(s1 - s0);
        float denom = 1.f + e1;
        g_slot_expert[2 * t + 0] = i0;
        g_slot_expert[2 * t + 1] = i1;
        g_slot_p[2 * t + 0] = 1.f / denom;
        g_slot_p[2 * t + 1] = e1 / denom;
    }
}

// ---------------- 2) ordered capacity assignment ----------------
__global__ void assign_kernel()
{
    const int T = 256;
    const int CH = SLOTS / T;
    int tid = threadIdx.x;
    int base = tid * CH;

    __shared__ int   scnt[T][EE];
    __shared__ float simp[T][EE];

    int lc[EE];
#pragma unroll
    for (int e = 0; e < EE; e++) lc[e] = 0;
    for (int i = 0; i < CH; i++) lc[g_slot_expert[base + i]]++;
#pragma unroll
    for (int e = 0; e < EE; e++) scnt[tid][e] = lc[e];
    __syncthreads();

    if (tid < EE) {
        int e = tid, run = 0;
        for (int t2 = 0; t2 < T; t2++) { int c = scnt[t2][e]; scnt[t2][e] = run; run += c; }
        g_cnt[e] = min(run, CAP);
    }
    __syncthreads();

    int off[EE];
    float impl[EE];
#pragma unroll
    for (int e = 0; e < EE; e++) { off[e] = scnt[tid][e]; impl[e] = 0.f; }

    for (int i = 0; i < CH; i += 2) {
        int sA = base + i, sBs = base + i + 1;
        int e0 = g_slot_expert[sA], e1 = g_slot_expert[sBs];
        int p0 = off[e0]++;
        int p1 = off[e1]++;
        bool k0 = p0 < CAP, k1 = p1 < CAP;
        float w0 = k0 ? g_slot_p[sA] : 0.f;
        float w1 = k1 ? g_slot_p[sBs] : 0.f;
        float s = w0 + w1 + EPS_F;
        w0 /= s; w1 /= s;
        bool v0 = w0 > 0.f, v1 = w1 > 0.f;
        g_slot_w[sA] = w0;
        g_slot_w[sBs] = w1;
        g_slot_pos[sA]  = v0 ? p0 : -1;
        g_slot_pos[sBs] = v1 ? p1 : -1;
        if (v0) impl[e0] += w0;
        if (v1) impl[e1] += w1;
    }
#pragma unroll
    for (int e = 0; e < EE; e++) simp[tid][e] = impl[e];
    __syncthreads();
    if (tid < EE) {
        int e = tid;
        float s = 0.f;
        for (int t2 = 0; t2 < T; t2++) s += simp[t2][e];
        g_imp[e] = s;
    }
}

// ---------------- 3) dispatch ----------------
__global__ void dispatch_kernel(const float* __restrict__ x)
{
    int slot = blockIdx.x;
    int pos = g_slot_pos[slot];
    if (pos < 0) return;
    int e = g_slot_expert[slot];
    float w = g_slot_w[slot];
    int tok = slot >> 1;
    const float4* xs = (const float4*)(x + (size_t)tok * DD);
    size_t rowbase = ((size_t)(e * CAP + pos)) * (DD / 2);
    int i = threadIdx.x;                    // 256 threads
    float4 v = xs[i];
    unsigned h0, l0, h1, l1;
    split2(v.x * w, v.y * w, h0, l0);
    split2(v.z * w, v.w * w, h1, l1);
    g_Xhi[rowbase + 2 * i + 0] = h0;  g_Xlo[rowbase + 2 * i + 0] = l0;
    g_Xhi[rowbase + 2 * i + 1] = h1;  g_Xlo[rowbase + 2 * i + 1] = l1;
}

// ---------------- weight split ----------------
__global__ void wsplit_kernel(const float* __restrict__ W,
                              unsigned* __restrict__ hi, unsigned* __restrict__ lo, int n2)
{
    int i = blockIdx.x * blockDim.x + threadIdx.x;
    int stride = gridDim.x * blockDim.x;
    for (; i < n2; i += stride) {
        float2 v = ((const float2*)W)[i];
        unsigned h, l;
        split2(v.x, v.y, h, l);
        hi[i] = h; lo[i] = l;
    }
}

// ---------------- ldmatrix + mma.sync NT GEMM (bf16 3-split) ----------------
// C[m,n] = sum_k A[m,k]*B[n,k].  CTA tile 128x256x32, 16 warps (2x8), warp 64x32.
// 3-stage cp.async ring.
#define PITCH 20                   // u32 per 32-bf16 row (16 data + 4 pad); LDSM conflict-free
#define A_U32 (128 * PITCH)        // A operand per stage: 2560 u32
#define B_U32 (256 * PITCH)        // B operand per stage: 5120 u32
#define STAGE_U32 (2 * A_U32 + 2 * B_U32)   // Ah, Al, Bh, Bl: 15360 u32 (60 KB)
#define NSTAGE 3
#define GEMM_SMEM_BYTES (NSTAGE * STAGE_U32 * 4)   // 184320 B
static_assert(GEMM_SMEM_BYTES <= 227 * 1024, "smem");

template<bool FUSE_RELU_SPLIT>
__global__ __launch_bounds__(512, 1)
void gemm_tc_kernel(const unsigned* __restrict__ Ahi, const unsigned* __restrict__ Alo,
                    const unsigned* __restrict__ Bhi, const unsigned* __restrict__ Blo,
                    float* __restrict__ Cf, unsigned* __restrict__ Chi, unsigned* __restrict__ Clo,
                    int Nn, int Kk,
                    int strideA2, int strideB2, int strideC)
{
    extern __shared__ unsigned smem[];

    int e = blockIdx.z;
    int M = g_cnt[e];
    int m0 = blockIdx.y * 128;
    if (m0 >= M) return;
    int n0 = blockIdx.x * 256;
    int K2 = Kk >> 1;

    const unsigned* Ah = Ahi + (size_t)e * strideA2;
    const unsigned* Al = Alo + (size_t)e * strideA2;
    const unsigned* Bh = Bhi + (size_t)e * strideB2;
    const unsigned* Bl = Blo + (size_t)e * strideB2;

    int tid = threadIdx.x;
    int lane = tid & 31, warp = tid >> 5;
    int wm = warp >> 3, wn = warp & 7;      // 2 x 8 warps, warp tile 64x32

    uint32_t sbase = smem_u32(smem);

    // loader mapping: 4 threads/row; thread covers u32 [c0, c0+4)
    int lrow = tid >> 2;                    // 0..127
    int c0 = (tid & 3) * 4;
    int gm = m0 + lrow;
    int gmc = min(gm, M - 1);

    // LDSM per-lane geometry
    int aRow  = wm * 64 + (lane & 15);            // + mi*16
    int aHalf = lane >> 4;                        // k-half 0/1
    int bRow  = wn * 32 + (lane & 7) + ((lane >> 4) << 3);  // + ni2*16
    int bHalf = (lane >> 3) & 1;

    float acc[4][4][4];
#pragma unroll
    for (int mi = 0; mi < 4; mi++)
#pragma unroll
        for (int ni = 0; ni < 4; ni++)
#pragma unroll
            for (int q = 0; q < 4; q++) acc[mi][ni][q] = 0.f;

    int nch = Kk / 32;

    auto issue = [&](int it) {
        uint32_t soff = (uint32_t)(it % NSTAGE) * STAGE_U32;
        int kt2 = it * 16;
        // A: 128 rows x 16 u32, 512 threads x 4 u32 = exact cover
        {
            uint32_t dst = sbase + (uint32_t)(soff + lrow * PITCH + c0) * 4;
            size_t ga = (size_t)gmc * K2 + kt2 + c0;
            cpa16(dst,             Ah + ga);
            cpa16(dst + A_U32 * 4, Al + ga);
        }
        // B: 256 rows x 16 u32, 2 chunks per thread
#pragma unroll
        for (int j = 0; j < 2; j++) {
            int idx = tid + j * 512;
            int r = idx >> 2;
            int cc = (idx & 3) * 4;
            uint32_t dst = sbase + (uint32_t)(soff + 2 * A_U32 + r * PITCH + cc) * 4;
            size_t gb = (size_t)(n0 + r) * K2 + kt2 + cc;
            cpa16(dst,             Bh + gb);
            cpa16(dst + B_U32 * 4, Bl + gb);
        }
        cpa_commit();
    };

    issue(0);
    issue(1);

    for (int it = 0; it < nch; it++) {
        if (it + 1 < nch) asm volatile("cp.async.wait_group 1;\n" ::: "memory");
        else              asm volatile("cp.async.wait_group 0;\n" ::: "memory");
        __syncthreads();

        if (it + 2 < nch) issue(it + 2);     // refills buffer (it-1)%3, freed by the sync

        uint32_t sA_h = sbase + (uint32_t)((it % NSTAGE) * STAGE_U32) * 4;
        uint32_t sA_l = sA_h + A_U32 * 4;
        uint32_t sB_h = sA_h + 2 * A_U32 * 4;
        uint32_t sB_l = sB_h + B_U32 * 4;

#pragma unroll
        for (int ks = 0; ks < 2; ks++) {
            int kb = ks * 8;
            uint32_t bh[2][4], bl[2][4];
#pragma unroll
            for (int n2 = 0; n2 < 2; n2++) {
                uint32_t ao = (uint32_t)((bRow + n2 * 16) * PITCH + kb + bHalf * 4) * 4;
                ldsm4(bh[n2], sB_h + ao);
                ldsm4(bl[n2], sB_l + ao);
            }
#pragma unroll
            for (int mi = 0; mi < 4; mi++) {
                uint32_t ah[4], al[4];
                uint32_t ao = (uint32_t)((aRow + mi * 16) * PITCH + kb + aHalf * 4) * 4;
                ldsm4(ah, sA_h + ao);
                ldsm4(al, sA_l + ao);
#pragma unroll
                for (int ni = 0; ni < 4; ni++) {
                    const uint32_t* bph = &bh[ni >> 1][(ni & 1) * 2];
                    const uint32_t* bpl = &bl[ni >> 1][(ni & 1) * 2];
                    mma16816(acc[mi][ni], ah, bph);
                    mma16816(acc[mi][ni], ah, bpl);
                    mma16816(acc[mi][ni], al, bph);
                }
            }
        }
        __syncthreads();   // all warps done with buffer `it` before it is refilled
    }

    // --- epilogue ---
#pragma unroll
    for (int mi = 0; mi < 4; mi++) {
#pragma unroll
        for (int ni = 0; ni < 4; ni++) {
            int r0 = m0 + wm * 64 + mi * 16 + (lane >> 2);
            int cc = n0 + wn * 32 + ni * 8 + 2 * (lane & 3);
            float* a = acc[mi][ni];
            if (FUSE_RELU_SPLIT) {
                size_t eoff = (size_t)e * ((size_t)CAP * (Nn >> 1));
                if (r0 < M) {
                    unsigned h, l;
                    split2(fmaxf(a[0], 0.f), fmaxf(a[1], 0.f), h, l);
                    size_t idx = eoff + (size_t)r0 * (Nn >> 1) + (cc >> 1);
                    Chi[idx] = h; Clo[idx] = l;
                }
                if (r0 + 8 < M) {
                    unsigned h, l;
                    split2(fmaxf(a[2], 0.f), fmaxf(a[3], 0.f), h, l);
                    size_t idx = eoff + (size_t)(r0 + 8) * (Nn >> 1) + (cc >> 1);
                    Chi[idx] = h; Clo[idx] = l;
                }
            } else {
                size_t eoff = (size_t)e * strideC;
                if (r0 < M)
                    *(float2*)(Cf + eoff + (size_t)r0 * Nn + cc) = make_float2(a[0], a[1]);
                if (r0 + 8 < M)
                    *(float2*)(Cf + eoff + (size_t)(r0 + 8) * Nn + cc) = make_float2(a[2], a[3]);
            }
        }
    }
}

// ---------------- 6) combine ----------------
__global__ void combine_kernel(float* __restrict__ y)
{
    int t = blockIdx.x;
    int i = threadIdx.x;
    float4 acc = make_float4(0.f, 0.f, 0.f, 0.f);
#pragma unroll
    for (int j = 0; j < KTOP; j++) {
        int slot = t * KTOP + j;
        int pos = g_slot_pos[slot];
        if (pos >= 0) {
            int e = g_slot_expert[slot];
            const float4* o = (const float4*)(g_Xbuf + ((size_t)(e * CAP + pos)) * DD);
            float4 v = o[i];
            acc.x += v.x; acc.y += v.y; acc.z += v.z; acc.w += v.w;
        }
    }
    ((float4*)(y + (size_t)t * DD))[i] = acc;
}

// ---------------- 7) aux loss ----------------
__global__ void aux_kernel(float* __restrict__ out, int out_size)
{
    float tc = 0.f, ic = 0.f;
#pragma unroll
    for (int e = 0; e < EE; e++) { tc += (float)g_cnt[e]; ic += g_imp[e]; }
    float aux = 0.f;
#pragma unroll
    for (int e = 0; e < EE; e++) aux += ((float)g_cnt[e] / tc) * (g_imp[e] / ic);
    out[out_size - 1] = aux * (float)EE;
}

// ---------------- launch ----------------
extern "C" void kernel_launch(void* const* d_in, const int* in_sizes, int n_in,
                              void* d_out, int out_size)
{
    const float* x  = (const float*)d_in[0];
    const float* Wg = (const float*)d_in[1];
    const float* W1 = (const float*)d_in[2];
    const float* W2 = (const float*)d_in[3];
    float* y = (float*)d_out;
    (void)in_sizes; (void)n_in;

    cudaFuncSetAttribute(gemm_tc_kernel<true>,  cudaFuncAttributeMaxDynamicSharedMemorySize, GEMM_SMEM_BYTES);
    cudaFuncSetAttribute(gemm_tc_kernel<false>, cudaFuncAttributeMaxDynamicSharedMemorySize, GEMM_SMEM_BYTES);

    cudaMemsetAsync(d_out, 0, (size_t)out_size * sizeof(float));

    gating_kernel<<<NN, 128>>>(x, Wg);
    assign_kernel<<<1, 256>>>();
    dispatch_kernel<<<SLOTS, 256>>>(x);

    unsigned *Xhi, *Xlo, *Hhi, *Hlo, *W1hi, *W1lo, *W2hi, *W2lo;
    float *Xbuf;
    cudaGetSymbolAddress((void**)&Xhi,  g_Xhi);
    cudaGetSymbolAddress((void**)&Xlo,  g_Xlo);
    cudaGetSymbolAddress((void**)&Hhi,  g_Hhi);
    cudaGetSymbolAddress((void**)&Hlo,  g_Hlo);
    cudaGetSymbolAddress((void**)&W1hi, g_W1hi);
    cudaGetSymbolAddress((void**)&W1lo, g_W1lo);
    cudaGetSymbolAddress((void**)&W2hi, g_W2hi);
    cudaGetSymbolAddress((void**)&W2lo, g_W2lo);
    cudaGetSymbolAddress((void**)&Xbuf, g_Xbuf);

    wsplit_kernel<<<2048, 256>>>(W1, W1hi, W1lo, EE * DFF * DD / 2);
    wsplit_kernel<<<2048, 256>>>(W2, W2hi, W2lo, EE * DD * DFF / 2);

    // GEMM1: H = relu(X @ W1^T); per expert M=cnt, N=DFF, K=DD; fused relu+split output
    {
        dim3 grid(DFF / 256, (CAP + 127) / 128, EE);
        gemm_tc_kernel<true><<<grid, 512, GEMM_SMEM_BYTES>>>(
            Xhi, Xlo, W1hi, W1lo, nullptr, Hhi, Hlo,
            DFF, DD, CAP * DD / 2, DFF * DD / 2, 0);
    }
    // GEMM2: Out = H @ W2^T; per expert M=cnt, N=DD, K=DFF; fp32 output
    {
        dim3 grid(DD / 256, (CAP + 127) / 128, EE);
        gemm_tc_kernel<false><<<grid, 512, GEMM_SMEM_BYTES>>>(
            Hhi, Hlo, W2hi, W2lo, Xbuf, nullptr, nullptr,
            DD, DFF, CAP * DFF / 2, DD * DFF / 2, CAP * DD);
    }

    combine_kernel<<<NN, 256>>>(y);
    aux_kernel<<<1, 1>>>(y, out_size);
}

// round 9
// speedup vs baseline: 2.4951x; 1.1386x over previous
#include <cuda_runtime.h>
#include <cuda_bf16.h>
#include <stdint.h>
#include <math.h>

// Problem constants
#define BB   4
#define SS   2048
#define DD   1024
#define DFF  4096
#define EE   8
#define NN   (BB*SS)          // 8192 tokens
#define KTOP 2
#define SLOTS (NN*KTOP)       // 16384
#define CAP  1280
#define EPS_F 1e-9f
#define NSPLIT2 4             // split-K factor for GEMM2

// ---------------- device scratch ----------------
__device__ float    g_Part[NSPLIT2 * EE * CAP * DD];  // GEMM2 split-K partials (~167MB)
__device__ unsigned g_Xhi[EE * CAP * DD / 2];     // dispatched X, bf16x2 hi
__device__ unsigned g_Xlo[EE * CAP * DD / 2];
__device__ unsigned g_Hhi[EE * CAP * DFF / 2];    // hidden, bf16x2 hi
__device__ unsigned g_Hlo[EE * CAP * DFF / 2];
__device__ unsigned g_W1hi[EE * DFF * DD / 2];
__device__ unsigned g_W1lo[EE * DFF * DD / 2];
__device__ unsigned g_W2hi[EE * DD * DFF / 2];
__device__ unsigned g_W2lo[EE * DD * DFF / 2];
__device__ int   g_slot_expert[SLOTS];
__device__ int   g_slot_pos[SLOTS];
__device__ float g_slot_p[SLOTS];
__device__ float g_slot_w[SLOTS];
__device__ int   g_cnt[EE];
__device__ float g_imp[EE];

// ---------------- helpers ----------------
__device__ __forceinline__ void split2(float v0, float v1, unsigned &hi, unsigned &lo)
{
    __nv_bfloat16 h0 = __float2bfloat16(v0);
    __nv_bfloat16 h1 = __float2bfloat16(v1);
    float r0 = v0 - __bfloat162float(h0);
    float r1 = v1 - __bfloat162float(h1);
    __nv_bfloat16 l0 = __float2bfloat16(r0);
    __nv_bfloat16 l1 = __float2bfloat16(r1);
    hi = ((unsigned)__bfloat16_as_ushort(h1) << 16) | (unsigned)__bfloat16_as_ushort(h0);
    lo = ((unsigned)__bfloat16_as_ushort(l1) << 16) | (unsigned)__bfloat16_as_ushort(l0);
}

__device__ __forceinline__ void mma16816(float c[4], const uint32_t a[4], const uint32_t b[2])
{
    asm volatile(
        "mma.sync.aligned.m16n8k16.row.col.f32.bf16.bf16.f32 "
        "{%0,%1,%2,%3},{%4,%5,%6,%7},{%8,%9},{%0,%1,%2,%3};\n"
        : "+f"(c[0]), "+f"(c[1]), "+f"(c[2]), "+f"(c[3])
        : "r"(a[0]), "r"(a[1]), "r"(a[2]), "r"(a[3]), "r"(b[0]), "r"(b[1]));
}

__device__ __forceinline__ void ldsm4(uint32_t r[4], uint32_t saddr)
{
    asm volatile("ldmatrix.sync.aligned.m8n8.x4.shared.b16 {%0,%1,%2,%3}, [%4];"
                 : "=r"(r[0]), "=r"(r[1]), "=r"(r[2]), "=r"(r[3]) : "r"(saddr));
}

__device__ __forceinline__ void cpa16(uint32_t saddr, const void* g)
{
    asm volatile("cp.async.cg.shared.global [%0], [%1], 16;\n" :: "r"(saddr), "l"(g));
}
__device__ __forceinline__ void cpa_commit() { asm volatile("cp.async.commit_group;\n"); }

__device__ __forceinline__ uint32_t smem_u32(const void* p) {
    uint32_t a;
    asm("{ .reg .u64 t; cvta.to.shared.u64 t, %1; cvt.u32.u64 %0, t; }" : "=r"(a) : "l"(p));
    return a;
}

// ---------------- 1) gating ----------------
__global__ void gating_kernel(const float* __restrict__ x, const float* __restrict__ Wg)
{
    int t = blockIdx.x;
    int tid = threadIdx.x;                  // 128 threads
    const float4* xv = (const float4*)(x + (size_t)t * DD);

    float acc[EE];
#pragma unroll
    for (int e = 0; e < EE; e++) acc[e] = 0.f;

    for (int i = tid; i < DD / 4; i += 128) {
        float4 xx = xv[i];
#pragma unroll
        for (int e = 0; e < EE; e++) {
            float4 wv = *(const float4*)(Wg + (size_t)e * DD + i * 4);
            acc[e] += xx.x * wv.x + xx.y * wv.y + xx.z * wv.z + xx.w * wv.w;
        }
    }

    __shared__ float sh[EE][128];
#pragma unroll
    for (int e = 0; e < EE; e++) sh[e][tid] = acc[e];
    __syncthreads();
    for (int s = 64; s > 0; s >>= 1) {
        if (tid < s) {
#pragma unroll
            for (int e = 0; e < EE; e++) sh[e][tid] += sh[e][tid + s];
        }
        __syncthreads();
    }

    if (tid == 0) {
        float v[EE];
#pragma unroll
        for (int e = 0; e < EE; e++) v[e] = sh[e][0];
        int i0 = 0; float s0 = v[0];
#pragma unroll
        for (int e = 1; e < EE; e++) if (v[e] > s0) { s0 = v[e]; i0 = e; }
        int i1 = -1; float s1 = -INFINITY;
#pragma unroll
        for (int e = 0; e < EE; e++) if (e != i0 && v[e] > s1) { s1 = v[e]; i1 = e; }
        float e1 = expf(s1 - s0);
        float denom = 1.f + e1;
        g_slot_expert[2 * t + 0] = i0;
        g_slot_expert[2 * t + 1] = i1;
        g_slot_p[2 * t + 0] = 1.f / denom;
        g_slot_p[2 * t + 1] = e1 / denom;
    }
}

// ---------------- 2) ordered capacity assignment ----------------
__global__ void assign_kernel()
{
    const int T = 256;
    const int CH = SLOTS / T;
    int tid = threadIdx.x;
    int base = tid * CH;

    __shared__ int   scnt[T][EE];
    __shared__ float simp[T][EE];

    int lc[EE];
#pragma unroll
    for (int e = 0; e < EE; e++) lc[e] = 0;
    for (int i = 0; i < CH; i++) lc[g_slot_expert[base + i]]++;
#pragma unroll
    for (int e = 0; e < EE; e++) scnt[tid][e] = lc[e];
    __syncthreads();

    if (tid < EE) {
        int e = tid, run = 0;
        for (int t2 = 0; t2 < T; t2++) { int c = scnt[t2][e]; scnt[t2][e] = run; run += c; }
        g_cnt[e] = min(run, CAP);
    }
    __syncthreads();

    int off[EE];
    float impl[EE];
#pragma unroll
    for (int e = 0; e < EE; e++) { off[e] = scnt[tid][e]; impl[e] = 0.f; }

    for (int i = 0; i < CH; i += 2) {
        int sA = base + i, sBs = base + i + 1;
        int e0 = g_slot_expert[sA], e1 = g_slot_expert[sBs];
        int p0 = off[e0]++;
        int p1 = off[e1]++;
        bool k0 = p0 < CAP, k1 = p1 < CAP;
        float w0 = k0 ? g_slot_p[sA] : 0.f;
        float w1 = k1 ? g_slot_p[sBs] : 0.f;
        float s = w0 + w1 + EPS_F;
        w0 /= s; w1 /= s;
        bool v0 = w0 > 0.f, v1 = w1 > 0.f;
        g_slot_w[sA] = w0;
        g_slot_w[sBs] = w1;
        g_slot_pos[sA]  = v0 ? p0 : -1;
        g_slot_pos[sBs] = v1 ? p1 : -1;
        if (v0) impl[e0] += w0;
        if (v1) impl[e1] += w1;
    }
#pragma unroll
    for (int e = 0; e < EE; e++) simp[tid][e] = impl[e];
    __syncthreads();
    if (tid < EE) {
        int e = tid;
        float s = 0.f;
        for (int t2 = 0; t2 < T; t2++) s += simp[t2][e];
        g_imp[e] = s;
    }
}

// ---------------- 3) dispatch ----------------
__global__ void dispatch_kernel(const float* __restrict__ x)
{
    int slot = blockIdx.x;
    int pos = g_slot_pos[slot];
    if (pos < 0) return;
    int e = g_slot_expert[slot];
    float w = g_slot_w[slot];
    int tok = slot >> 1;
    const float4* xs = (const float4*)(x + (size_t)tok * DD);
    size_t rowbase = ((size_t)(e * CAP + pos)) * (DD / 2);
    int i = threadIdx.x;                    // 256 threads
    float4 v = xs[i];
    unsigned h0, l0, h1, l1;
    split2(v.x * w, v.y * w, h0, l0);
    split2(v.z * w, v.w * w, h1, l1);
    g_Xhi[rowbase + 2 * i + 0] = h0;  g_Xlo[rowbase + 2 * i + 0] = l0;
    g_Xhi[rowbase + 2 * i + 1] = h1;  g_Xlo[rowbase + 2 * i + 1] = l1;
}

// ---------------- weight split ----------------
__global__ void wsplit_kernel(const float* __restrict__ W,
                              unsigned* __restrict__ hi, unsigned* __restrict__ lo, int n2)
{
    int i = blockIdx.x * blockDim.x + threadIdx.x;
    int stride = gridDim.x * blockDim.x;
    for (; i < n2; i += stride) {
        float2 v = ((const float2*)W)[i];
        unsigned h, l;
        split2(v.x, v.y, h, l);
        hi[i] = h; lo[i] = l;
    }
}

// ---------------- ldmatrix + mma.sync NT GEMM (bf16 3-split) ----------------
// C[m,n] = sum_k A[m,k]*B[n,k].  CTA tile 128x256x32, 16 warps (2x8), warp 64x32.
// 3-stage cp.async ring, ONE __syncthreads per chunk. Optional split-K.
#define PITCH 20                   // u32 per 32-bf16 row (16 data + 4 pad); LDSM conflict-free
#define A_U32 (128 * PITCH)        // A operand per stage: 2560 u32
#define B_U32 (256 * PITCH)        // B operand per stage: 5120 u32
#define STAGE_U32 (2 * A_U32 + 2 * B_U32)   // Ah, Al, Bh, Bl: 15360 u32 (60 KB)
#define NSTAGE 3
#define GEMM_SMEM_BYTES (NSTAGE * STAGE_U32 * 4)   // 184320 B
static_assert(GEMM_SMEM_BYTES <= 227 * 1024, "smem");

template<bool FUSE_RELU_SPLIT>
__global__ __launch_bounds__(512, 1)
void gemm_tc_kernel(const unsigned* __restrict__ Ahi, const unsigned* __restrict__ Alo,
                    const unsigned* __restrict__ Bhi, const unsigned* __restrict__ Blo,
                    float* __restrict__ Cf, unsigned* __restrict__ Chi, unsigned* __restrict__ Clo,
                    int Nn, int Kfull, int Klen, int nsplit, long long partStride,
                    int strideA2, int strideB2, int strideC)
{
    extern __shared__ unsigned smem[];

    int zs = blockIdx.z;
    int e  = zs / nsplit;
    int sp = zs - e * nsplit;
    int M = g_cnt[e];
    int m0 = blockIdx.y * 128;
    if (m0 >= M) return;
    int n0 = blockIdx.x * 256;
    int K2 = Kfull >> 1;
    int k0_2 = sp * (Klen >> 1);

    const unsigned* Ah = Ahi + (size_t)e * strideA2 + k0_2;
    const unsigned* Al = Alo + (size_t)e * strideA2 + k0_2;
    const unsigned* Bh = Bhi + (size_t)e * strideB2 + k0_2;
    const unsigned* Bl = Blo + (size_t)e * strideB2 + k0_2;

    int tid = threadIdx.x;
    int lane = tid & 31, warp = tid >> 5;
    int wm = warp >> 3, wn = warp & 7;      // 2 x 8 warps, warp tile 64x32

    uint32_t sbase = smem_u32(smem);

    // loader mapping: 4 threads/row; thread covers u32 [c0, c0+4)
    int lrow = tid >> 2;                    // 0..127
    int c0 = (tid & 3) * 4;
    int gm = m0 + lrow;
    int gmc = min(gm, M - 1);

    // LDSM per-lane geometry
    int aRow  = wm * 64 + (lane & 15);            // + mi*16
    int aHalf = lane >> 4;                        // k-half 0/1
    int bRow  = wn * 32 + (lane & 7) + ((lane >> 4) << 3);  // + ni2*16
    int bHalf = (lane >> 3) & 1;

    float acc[4][4][4];
#pragma unroll
    for (int mi = 0; mi < 4; mi++)
#pragma unroll
        for (int ni = 0; ni < 4; ni++)
#pragma unroll
            for (int q = 0; q < 4; q++) acc[mi][ni][q] = 0.f;

    int nch = Klen / 32;

    auto issue = [&](int it) {
        uint32_t soff = (uint32_t)(it % NSTAGE) * STAGE_U32;
        int kt2 = it * 16;
        // A: 128 rows x 16 u32, 512 threads x 4 u32 = exact cover
        {
            uint32_t dst = sbase + (uint32_t)(soff + lrow * PITCH + c0) * 4;
            size_t ga = (size_t)gmc * K2 + kt2 + c0;
            cpa16(dst,             Ah + ga);
            cpa16(dst + A_U32 * 4, Al + ga);
        }
        // B: 256 rows x 16 u32, 2 chunks per thread
#pragma unroll
        for (int j = 0; j < 2; j++) {
            int idx = tid + j * 512;
            int r = idx >> 2;
            int cc = (idx & 3) * 4;
            uint32_t dst = sbase + (uint32_t)(soff + 2 * A_U32 + r * PITCH + cc) * 4;
            size_t gb = (size_t)(n0 + r) * K2 + kt2 + cc;
            cpa16(dst,             Bh + gb);
            cpa16(dst + B_U32 * 4, Bl + gb);
        }
        cpa_commit();
    };

    issue(0);
    issue(1);

    for (int it = 0; it < nch; it++) {
        if (it + 1 < nch) asm volatile("cp.async.wait_group 1;\n" ::: "memory");
        else              asm volatile("cp.async.wait_group 0;\n" ::: "memory");
        __syncthreads();   // all warps done with stage (it-1)%3 (freed) and stage it%3 ready

        if (it + 2 < nch) issue(it + 2);     // refills stage (it-1)%3

        uint32_t sA_h = sbase + (uint32_t)((it % NSTAGE) * STAGE_U32) * 4;
        uint32_t sA_l = sA_h + A_U32 * 4;
        uint32_t sB_h = sA_h + 2 * A_U32 * 4;
        uint32_t sB_l = sB_h + B_U32 * 4;

#pragma unroll
        for (int ks = 0; ks < 2; ks++) {
            int kb = ks * 8;
            uint32_t bh[2][4], bl[2][4];
#pragma unroll
            for (int n2 = 0; n2 < 2; n2++) {
                uint32_t ao = (uint32_t)((bRow + n2 * 16) * PITCH + kb + bHalf * 4) * 4;
                ldsm4(bh[n2], sB_h + ao);
                ldsm4(bl[n2], sB_l + ao);
            }
#pragma unroll
            for (int mi = 0; mi < 4; mi++) {
                uint32_t ah[4], al[4];
                uint32_t ao = (uint32_t)((aRow + mi * 16) * PITCH + kb + aHalf * 4) * 4;
                ldsm4(ah, sA_h + ao);
                ldsm4(al, sA_l + ao);
#pragma unroll
                for (int ni = 0; ni < 4; ni++) {
                    const uint32_t* bph = &bh[ni >> 1][(ni & 1) * 2];
                    const uint32_t* bpl = &bl[ni >> 1][(ni & 1) * 2];
                    mma16816(acc[mi][ni], ah, bph);
                    mma16816(acc[mi][ni], ah, bpl);
                    mma16816(acc[mi][ni], al, bph);
                }
            }
        }
    }

    // --- epilogue ---
#pragma unroll
    for (int mi = 0; mi < 4; mi++) {
#pragma unroll
        for (int ni = 0; ni < 4; ni++) {
            int r0 = m0 + wm * 64 + mi * 16 + (lane >> 2);
            int cc = n0 + wn * 32 + ni * 8 + 2 * (lane & 3);
            float* a = acc[mi][ni];
            if (FUSE_RELU_SPLIT) {
                size_t eoff = (size_t)e * ((size_t)CAP * (Nn >> 1));
                if (r0 < M) {
                    unsigned h, l;
                    split2(fmaxf(a[0], 0.f), fmaxf(a[1], 0.f), h, l);
                    size_t idx = eoff + (size_t)r0 * (Nn >> 1) + (cc >> 1);
                    Chi[idx] = h; Clo[idx] = l;
                }
                if (r0 + 8 < M) {
                    unsigned h, l;
                    split2(fmaxf(a[2], 0.f), fmaxf(a[3], 0.f), h, l);
                    size_t idx = eoff + (size_t)(r0 + 8) * (Nn >> 1) + (cc >> 1);
                    Chi[idx] = h; Clo[idx] = l;
                }
            } else {
                float* Cp = Cf + (long long)sp * partStride + (size_t)e * strideC;
                if (r0 < M)
                    *(float2*)(Cp + (size_t)r0 * Nn + cc) = make_float2(a[0], a[1]);
                if (r0 + 8 < M)
                    *(float2*)(Cp + (size_t)(r0 + 8) * Nn + cc) = make_float2(a[2], a[3]);
            }
        }
    }
}

// ---------------- 6) combine: sum split-K partials over kept slots ----------------
__global__ void combine_kernel(float* __restrict__ y)
{
    int t = blockIdx.x;
    int i = threadIdx.x;
    const long long PS = (long long)EE * CAP * DD;
    float4 acc = make_float4(0.f, 0.f, 0.f, 0.f);
#pragma unroll
    for (int j = 0; j < KTOP; j++) {
        int slot = t * KTOP + j;
        int pos = g_slot_pos[slot];
        if (pos >= 0) {
            int e = g_slot_expert[slot];
            size_t rb = ((size_t)(e * CAP + pos)) * DD;
#pragma unroll
            for (int s = 0; s < NSPLIT2; s++) {
                const float4* o = (const float4*)(g_Part + s * PS + rb);
                float4 v = o[i];
                acc.x += v.x; acc.y += v.y; acc.z += v.z; acc.w += v.w;
            }
        }
    }
    ((float4*)(y + (size_t)t * DD))[i] = acc;
}

// ---------------- 7) aux loss ----------------
__global__ void aux_kernel(float* __restrict__ out, int out_size)
{
    float tc = 0.f, ic = 0.f;
#pragma unroll
    for (int e = 0; e < EE; e++) { tc += (float)g_cnt[e]; ic += g_imp[e]; }
    float aux = 0.f;
#pragma unroll
    for (int e = 0; e < EE; e++) aux += ((float)g_cnt[e] / tc) * (g_imp[e] / ic);
    out[out_size - 1] = aux * (float)EE;
}

// ---------------- launch ----------------
extern "C" void kernel_launch(void* const* d_in, const int* in_sizes, int n_in,
                              void* d_out, int out_size)
{
    const float* x  = (const float*)d_in[0];
    const float* Wg = (const float*)d_in[1];
    const float* W1 = (const float*)d_in[2];
    const float* W2 = (const float*)d_in[3];
    float* y = (float*)d_out;
    (void)in_sizes; (void)n_in; (void)out_size;

    cudaFuncSetAttribute(gemm_tc_kernel<true>,  cudaFuncAttributeMaxDynamicSharedMemorySize, GEMM_SMEM_BYTES);
    cudaFuncSetAttribute(gemm_tc_kernel<false>, cudaFuncAttributeMaxDynamicSharedMemorySize, GEMM_SMEM_BYTES);

    unsigned *Xhi, *Xlo, *Hhi, *Hlo, *W1hi, *W1lo, *W2hi, *W2lo;
    float *Part;
    cudaGetSymbolAddress((void**)&Xhi,  g_Xhi);
    cudaGetSymbolAddress((void**)&Xlo,  g_Xlo);
    cudaGetSymbolAddress((void**)&Hhi,  g_Hhi);
    cudaGetSymbolAddress((void**)&Hlo,  g_Hlo);
    cudaGetSymbolAddress((void**)&W1hi, g_W1hi);
    cudaGetSymbolAddress((void**)&W1lo, g_W1lo);
    cudaGetSymbolAddress((void**)&W2hi, g_W2hi);
    cudaGetSymbolAddress((void**)&W2lo, g_W2lo);
    cudaGetSymbolAddress((void**)&Part, g_Part);

    // launch order chosen so GEMM1 is the 5th visible launch (ncu -s 5 -c 1)
    gating_kernel<<<NN, 128>>>(x, Wg);                                   // 1
    assign_kernel<<<1, 256>>>();                                         // 2
    dispatch_kernel<<<SLOTS, 256>>>(x);                                  // 3
    wsplit_kernel<<<2048, 256>>>(W1, W1hi, W1lo, EE * DFF * DD / 2);     // 4

    // GEMM1: H = relu(X @ W1^T); per expert M=cnt, N=DFF, K=DD; fused relu+split
    {
        dim3 grid(DFF / 256, CAP / 128, EE);                             // 5 (profiled)
        gemm_tc_kernel<true><<<grid, 512, GEMM_SMEM_BYTES>>>(
            Xhi, Xlo, W1hi, W1lo, nullptr, Hhi, Hlo,
            DFF, DD, DD, 1, 0,
            CAP * DD / 2, DFF * DD / 2, 0);
    }

    wsplit_kernel<<<2048, 256>>>(W2, W2hi, W2lo, EE * DD * DFF / 2);     // 6

    // GEMM2: Part[s] = H[:, s*1024:(s+1)*1024] @ W2[:, s*1024:(s+1)*1024]^T (split-K x4)
    {
        dim3 grid(DD / 256, CAP / 128, EE * NSPLIT2);                    // 7
        gemm_tc_kernel<false><<<grid, 512, GEMM_SMEM_BYTES>>>(
            Hhi, Hlo, W2hi, W2lo, Part, nullptr, nullptr,
            DD, DFF, DFF / NSPLIT2, NSPLIT2, (long long)EE * CAP * DD,
            CAP * DFF / 2, DD * DFF / 2, CAP * DD);
    }

    combine_kernel<<<NN, 256>>>(y);                                      // 8
    aux_kernel<<<1, 1>>>(y, out_size);                                   // 9
}

// round 10
// speedup vs baseline: 3.2876x; 1.3176x over previous
#include <cuda_runtime.h>
#include <cuda_fp16.h>
#include <stdint.h>
#include <math.h>

// Problem constants
#define BB   4
#define SS   2048
#define DD   1024
#define DFF  4096
#define EE   8
#define NN   (BB*SS)          // 8192 tokens
#define KTOP 2
#define SLOTS (NN*KTOP)       // 16384
#define CAP  1280
#define EPS_F 1e-9f
#define NSPLIT2 4             // split-K factor for GEMM2

// ---------------- device scratch ----------------
__device__ float    g_Part[NSPLIT2 * EE * CAP * DD];  // GEMM2 split-K partials
__device__ unsigned g_Xhi[EE * CAP * DD / 2];     // dispatched X, fp16x2 hi
__device__ unsigned g_Xlo[EE * CAP * DD / 2];     // fp16x2 lo (residual)
__device__ unsigned g_Hhi[EE * CAP * DFF / 2];    // hidden, fp16x2 hi
__device__ unsigned g_Hlo[EE * CAP * DFF / 2];
__device__ unsigned g_W1h[EE * DFF * DD / 2];     // W1 as fp16x2 (hi only)
__device__ unsigned g_W2h[EE * DD * DFF / 2];     // W2 as fp16x2 (hi only)
__device__ int   g_slot_expert[SLOTS];
__device__ int   g_slot_pos[SLOTS];
__device__ float g_slot_p[SLOTS];
__device__ float g_slot_w[SLOTS];
__device__ int   g_cnt[EE];
__device__ float g_imp[EE];

// ---------------- helpers ----------------
__device__ __forceinline__ unsigned packh(__half a, __half b)
{
    return ((unsigned)__half_as_ushort(b) << 16) | (unsigned)__half_as_ushort(a);
}

// fp16 two-term split: v = hi + lo with |lo| <= 2^-12 |v|
__device__ __forceinline__ void split2h(float v0, float v1, unsigned &hi, unsigned &lo)
{
    __half h0 = __float2half_rn(v0);
    __half h1 = __float2half_rn(v1);
    float r0 = v0 - __half2float(h0);
    float r1 = v1 - __half2float(h1);
    hi = packh(h0, h1);
    lo = packh(__float2half_rn(r0), __float2half_rn(r1));
}

__device__ __forceinline__ void mma16816h(float c[4], const uint32_t a[4], const uint32_t b[2])
{
    asm volatile(
        "mma.sync.aligned.m16n8k16.row.col.f32.f16.f16.f32 "
        "{%0,%1,%2,%3},{%4,%5,%6,%7},{%8,%9},{%0,%1,%2,%3};\n"
        : "+f"(c[0]), "+f"(c[1]), "+f"(c[2]), "+f"(c[3])
        : "r"(a[0]), "r"(a[1]), "r"(a[2]), "r"(a[3]), "r"(b[0]), "r"(b[1]));
}

__device__ __forceinline__ void ldsm4(uint32_t r[4], uint32_t saddr)
{
    asm volatile("ldmatrix.sync.aligned.m8n8.x4.shared.b16 {%0,%1,%2,%3}, [%4];"
                 : "=r"(r[0]), "=r"(r[1]), "=r"(r[2]), "=r"(r[3]) : "r"(saddr));
}

__device__ __forceinline__ void cpa16(uint32_t saddr, const void* g)
{
    asm volatile("cp.async.cg.shared.global [%0], [%1], 16;\n" :: "r"(saddr), "l"(g));
}
__device__ __forceinline__ void cpa_commit() { asm volatile("cp.async.commit_group;\n"); }

__device__ __forceinline__ uint32_t smem_u32(const void* p) {
    uint32_t a;
    asm("{ .reg .u64 t; cvta.to.shared.u64 t, %1; cvt.u32.u64 %0, t; }" : "=r"(a) : "l"(p));
    return a;
}

// ---------------- 1) gating ----------------
__global__ void gating_kernel(const float* __restrict__ x, const float* __restrict__ Wg)
{
    int t = blockIdx.x;
    int tid = threadIdx.x;                  // 128 threads
    const float4* xv = (const float4*)(x + (size_t)t * DD);

    float acc[EE];
#pragma unroll
    for (int e = 0; e < EE; e++) acc[e] = 0.f;

    for (int i = tid; i < DD / 4; i += 128) {
        float4 xx = xv[i];
#pragma unroll
        for (int e = 0; e < EE; e++) {
            float4 wv = *(const float4*)(Wg + (size_t)e * DD + i * 4);
            acc[e] += xx.x * wv.x + xx.y * wv.y + xx.z * wv.z + xx.w * wv.w;
        }
    }

    __shared__ float sh[EE][128];
#pragma unroll
    for (int e = 0; e < EE; e++) sh[e][tid] = acc[e];
    __syncthreads();
    for (int s = 64; s > 0; s >>= 1) {
        if (tid < s) {
#pragma unroll
            for (int e = 0; e < EE; e++) sh[e][tid] += sh[e][tid + s];
        }
        __syncthreads();
    }

    if (tid == 0) {
        float v[EE];
#pragma unroll
        for (int e = 0; e < EE; e++) v[e] = sh[e][0];
        int i0 = 0; float s0 = v[0];
#pragma unroll
        for (int e = 1; e < EE; e++) if (v[e] > s0) { s0 = v[e]; i0 = e; }
        int i1 = -1; float s1 = -INFINITY;
#pragma unroll
        for (int e = 0; e < EE; e++) if (e != i0 && v[e] > s1) { s1 = v[e]; i1 = e; }
        float e1 = expf(s1 - s0);
        float denom = 1.f + e1;
        g_slot_expert[2 * t + 0] = i0;
        g_slot_expert[2 * t + 1] = i1;
        g_slot_p[2 * t + 0] = 1.f / denom;
        g_slot_p[2 * t + 1] = e1 / denom;
    }
}

// ---------------- 2) ordered capacity assignment ----------------
__global__ void assign_kernel()
{
    const int T = 256;
    const int CH = SLOTS / T;
    int tid = threadIdx.x;
    int base = tid * CH;

    __shared__ int   scnt[T][EE];
    __shared__ float simp[T][EE];

    int lc[EE];
#pragma unroll
    for (int e = 0; e < EE; e++) lc[e] = 0;
    for (int i = 0; i < CH; i++) lc[g_slot_expert[base + i]]++;
#pragma unroll
    for (int e = 0; e < EE; e++) scnt[tid][e] = lc[e];
    __syncthreads();

    if (tid < EE) {
        int e = tid, run = 0;
        for (int t2 = 0; t2 < T; t2++) { int c = scnt[t2][e]; scnt[t2][e] = run; run += c; }
        g_cnt[e] = min(run, CAP);
    }
    __syncthreads();

    int off[EE];
    float impl[EE];
#pragma unroll
    for (int e = 0; e < EE; e++) { off[e] = scnt[tid][e]; impl[e] = 0.f; }

    for (int i = 0; i < CH; i += 2) {
        int sA = base + i, sBs = base + i + 1;
        int e0 = g_slot_expert[sA], e1 = g_slot_expert[sBs];
        int p0 = off[e0]++;
        int p1 = off[e1]++;
        bool k0 = p0 < CAP, k1 = p1 < CAP;
        float w0 = k0 ? g_slot_p[sA] : 0.f;
        float w1 = k1 ? g_slot_p[sBs] : 0.f;
        float s = w0 + w1 + EPS_F;
        w0 /= s; w1 /= s;
        bool v0 = w0 > 0.f, v1 = w1 > 0.f;
        g_slot_w[sA] = w0;
        g_slot_w[sBs] = w1;
        g_slot_pos[sA]  = v0 ? p0 : -1;
        g_slot_pos[sBs] = v1 ? p1 : -1;
        if (v0) impl[e0] += w0;
        if (v1) impl[e1] += w1;
    }
#pragma unroll
    for (int e = 0; e < EE; e++) simp[tid][e] = impl[e];
    __syncthreads();
    if (tid < EE) {
        int e = tid;
        float s = 0.f;
        for (int t2 = 0; t2 < T; t2++) s += simp[t2][e];
        g_imp[e] = s;
    }
}

// ---------------- 3) dispatch: X -> fp16 hi/lo ----------------
__global__ void dispatch_kernel(const float* __restrict__ x)
{
    int slot = blockIdx.x;
    int pos = g_slot_pos[slot];
    if (pos < 0) return;
    int e = g_slot_expert[slot];
    float w = g_slot_w[slot];
    int tok = slot >> 1;
    const float4* xs = (const float4*)(x + (size_t)tok * DD);
    size_t rowbase = ((size_t)(e * CAP + pos)) * (DD / 2);
    int i = threadIdx.x;                    // 256 threads
    float4 v = xs[i];
    unsigned h0, l0, h1, l1;
    split2h(v.x * w, v.y * w, h0, l0);
    split2h(v.z * w, v.w * w, h1, l1);
    g_Xhi[rowbase + 2 * i + 0] = h0;  g_Xlo[rowbase + 2 * i + 0] = l0;
    g_Xhi[rowbase + 2 * i + 1] = h1;  g_Xlo[rowbase + 2 * i + 1] = l1;
}

// ---------------- weight convert: fp32 -> fp16 (hi only) ----------------
__global__ void wconv_kernel(const float* __restrict__ W, unsigned* __restrict__ hi, int n2)
{
    int i = blockIdx.x * blockDim.x + threadIdx.x;
    int stride = gridDim.x * blockDim.x;
    for (; i < n2; i += stride) {
        float2 v = ((const float2*)W)[i];
        hi[i] = packh(__float2half_rn(v.x), __float2half_rn(v.y));
    }
}

// ---------------- ldmatrix + mma.sync NT GEMM (fp16 2-product) ----------------
// C[m,n] = sum_k (Ahi+Alo)[m,k]*Bh[n,k].  CTA tile 128x256x32, 16 warps (2x8), warp 64x32.
// 3-stage cp.async ring, one __syncthreads per chunk. Optional split-K.
#define PITCH 20                   // u32 per 32-fp16 row (16 data + 4 pad); LDSM conflict-free
#define A_U32 (128 * PITCH)        // A operand per stage: 2560 u32
#define B_U32 (256 * PITCH)        // B operand per stage: 5120 u32
#define STAGE_U32 (2 * A_U32 + B_U32)      // Ah, Al, Bh: 10240 u32 (40 KB)
#define NSTAGE 3
#define GEMM_SMEM_BYTES (NSTAGE * STAGE_U32 * 4)   // 122880 B
static_assert(GEMM_SMEM_BYTES <= 227 * 1024, "smem");

template<bool FUSE_RELU_SPLIT>
__global__ __launch_bounds__(512, 1)
void gemm_tc_kernel(const unsigned* __restrict__ Ahi, const unsigned* __restrict__ Alo,
                    const unsigned* __restrict__ Bh,
                    float* __restrict__ Cf, unsigned* __restrict__ Chi, unsigned* __restrict__ Clo,
                    int Nn, int Kfull, int Klen, int nsplit, long long partStride,
                    int strideA2, int strideB2, int strideC)
{
    extern __shared__ unsigned smem[];

    int zs = blockIdx.z;
    int e  = zs / nsplit;
    int sp = zs - e * nsplit;
    int M = g_cnt[e];
    int m0 = blockIdx.y * 128;
    if (m0 >= M) return;
    int n0 = blockIdx.x * 256;
    int K2 = Kfull >> 1;
    int k0_2 = sp * (Klen >> 1);

    const unsigned* Ah = Ahi + (size_t)e * strideA2 + k0_2;
    const unsigned* Al = Alo + (size_t)e * strideA2 + k0_2;
    const unsigned* Bp = Bh  + (size_t)e * strideB2 + k0_2;

    int tid = threadIdx.x;
    int lane = tid & 31, warp = tid >> 5;
    int wm = warp >> 3, wn = warp & 7;      // 2 x 8 warps, warp tile 64x32

    uint32_t sbase = smem_u32(smem);

    // loader mapping: 4 threads/row; thread covers u32 [c0, c0+4)
    int lrow = tid >> 2;                    // 0..127
    int c0 = (tid & 3) * 4;
    int gm = m0 + lrow;
    int gmc = min(gm, M - 1);

    // LDSM per-lane geometry
    int aRow  = wm * 64 + (lane & 15);            // + mi*16
    int aHalf = lane >> 4;                        // k-half 0/1
    int bRow  = wn * 32 + (lane & 7) + ((lane >> 4) << 3);  // + ni2*16
    int bHalf = (lane >> 3) & 1;

    float acc[4][4][4];
#pragma unroll
    for (int mi = 0; mi < 4; mi++)
#pragma unroll
        for (int ni = 0; ni < 4; ni++)
#pragma unroll
            for (int q = 0; q < 4; q++) acc[mi][ni][q] = 0.f;

    int nch = Klen / 32;

    auto issue = [&](int it) {
        uint32_t soff = (uint32_t)(it % NSTAGE) * STAGE_U32;
        int kt2 = it * 16;
        // A: 128 rows x 16 u32, 512 threads x 4 u32 = exact cover (hi + lo)
        {
            uint32_t dst = sbase + (uint32_t)(soff + lrow * PITCH + c0) * 4;
            size_t ga = (size_t)gmc * K2 + kt2 + c0;
            cpa16(dst,             Ah + ga);
            cpa16(dst + A_U32 * 4, Al + ga);
        }
        // B: 256 rows x 16 u32 (hi only), 2 chunks per thread
#pragma unroll
        for (int j = 0; j < 2; j++) {
            int idx = tid + j * 512;
            int r = idx >> 2;
            int cc = (idx & 3) * 4;
            uint32_t dst = sbase + (uint32_t)(soff + 2 * A_U32 + r * PITCH + cc) * 4;
            size_t gb = (size_t)(n0 + r) * K2 + kt2 + cc;
            cpa16(dst, Bp + gb);
        }
        cpa_commit();
    };

    issue(0);
    issue(1);

    for (int it = 0; it < nch; it++) {
        if (it + 1 < nch) asm volatile("cp.async.wait_group 1;\n" ::: "memory");
        else              asm volatile("cp.async.wait_group 0;\n" ::: "memory");
        __syncthreads();   // stage it ready; stage (it-1)%3 free for refill

        if (it + 2 < nch) issue(it + 2);

        uint32_t sA_h = sbase + (uint32_t)((it % NSTAGE) * STAGE_U32) * 4;
        uint32_t sA_l = sA_h + A_U32 * 4;
        uint32_t sB_h = sA_h + 2 * A_U32 * 4;

#pragma unroll
        for (int ks = 0; ks < 2; ks++) {
            int kb = ks * 8;
            uint32_t bh[2][4];
#pragma unroll
            for (int n2 = 0; n2 < 2; n2++) {
                uint32_t ao = (uint32_t)((bRow + n2 * 16) * PITCH + kb + bHalf * 4) * 4;
                ldsm4(bh[n2], sB_h + ao);
            }
#pragma unroll
            for (int mi = 0; mi < 4; mi++) {
                uint32_t ah[4], al[4];
                uint32_t ao = (uint32_t)((aRow + mi * 16) * PITCH + kb + aHalf * 4) * 4;
                ldsm4(ah, sA_h + ao);
                ldsm4(al, sA_l + ao);
#pragma unroll
                for (int ni = 0; ni < 4; ni++) {
                    const uint32_t* bph = &bh[ni >> 1][(ni & 1) * 2];
                    mma16816h(acc[mi][ni], ah, bph);
                    mma16816h(acc[mi][ni], al, bph);
                }
            }
        }
    }

    // --- epilogue ---
#pragma unroll
    for (int mi = 0; mi < 4; mi++) {
#pragma unroll
        for (int ni = 0; ni < 4; ni++) {
            int r0 = m0 + wm * 64 + mi * 16 + (lane >> 2);
            int cc = n0 + wn * 32 + ni * 8 + 2 * (lane & 3);
            float* a = acc[mi][ni];
            if (FUSE_RELU_SPLIT) {
                size_t eoff = (size_t)e * ((size_t)CAP * (Nn >> 1));
                if (r0 < M) {
                    unsigned h, l;
                    split2h(fmaxf(a[0], 0.f), fmaxf(a[1], 0.f), h, l);
                    size_t idx = eoff + (size_t)r0 * (Nn >> 1) + (cc >> 1);
                    Chi[idx] = h; Clo[idx] = l;
                }
                if (r0 + 8 < M) {
                    unsigned h, l;
                    split2h(fmaxf(a[2], 0.f), fmaxf(a[3], 0.f), h, l);
                    size_t idx = eoff + (size_t)(r0 + 8) * (Nn >> 1) + (cc >> 1);
                    Chi[idx] = h; Clo[idx] = l;
                }
            } else {
                float* Cp = Cf + (long long)sp * partStride + (size_t)e * strideC;
                if (r0 < M)
                    *(float2*)(Cp + (size_t)r0 * Nn + cc) = make_float2(a[0], a[1]);
                if (r0 + 8 < M)
                    *(float2*)(Cp + (size_t)(r0 + 8) * Nn + cc) = make_float2(a[2], a[3]);
            }
        }
    }
}

// ---------------- 6) combine: sum split-K partials over kept slots ----------------
__global__ void combine_kernel(float* __restrict__ y)
{
    int t = blockIdx.x;
    int i = threadIdx.x;
    const long long PS = (long long)EE * CAP * DD;
    float4 acc = make_float4(0.f, 0.f, 0.f, 0.f);
#pragma unroll
    for (int j = 0; j < KTOP; j++) {
        int slot = t * KTOP + j;
        int pos = g_slot_pos[slot];
        if (pos >= 0) {
            int e = g_slot_expert[slot];
            size_t rb = ((size_t)(e * CAP + pos)) * DD;
#pragma unroll
            for (int s = 0; s < NSPLIT2; s++) {
                const float4* o = (const float4*)(g_Part + s * PS + rb);
                float4 v = o[i];
                acc.x += v.x; acc.y += v.y; acc.z += v.z; acc.w += v.w;
            }
        }
    }
    ((float4*)(y + (size_t)t * DD))[i] = acc;
}

// ---------------- 7) aux loss ----------------
__global__ void aux_kernel(float* __restrict__ out, int out_size)
{
    float tc = 0.f, ic = 0.f;
#pragma unroll
    for (int e = 0; e < EE; e++) { tc += (float)g_cnt[e]; ic += g_imp[e]; }
    float aux = 0.f;
#pragma unroll
    for (int e = 0; e < EE; e++) aux += ((float)g_cnt[e] / tc) * (g_imp[e] / ic);
    out[out_size - 1] = aux * (float)EE;
}

// ---------------- launch ----------------
extern "C" void kernel_launch(void* const* d_in, const int* in_sizes, int n_in,
                              void* d_out, int out_size)
{
    const float* x  = (const float*)d_in[0];
    const float* Wg = (const float*)d_in[1];
    const float* W1 = (const float*)d_in[2];
    const float* W2 = (const float*)d_in[3];
    float* y = (float*)d_out;
    (void)in_sizes; (void)n_in;

    cudaFuncSetAttribute(gemm_tc_kernel<true>,  cudaFuncAttributeMaxDynamicSharedMemorySize, GEMM_SMEM_BYTES);
    cudaFuncSetAttribute(gemm_tc_kernel<false>, cudaFuncAttributeMaxDynamicSharedMemorySize, GEMM_SMEM_BYTES);

    unsigned *Xhi, *Xlo, *Hhi, *Hlo, *W1h, *W2h;
    float *Part;
    cudaGetSymbolAddress((void**)&Xhi, g_Xhi);
    cudaGetSymbolAddress((void**)&Xlo, g_Xlo);
    cudaGetSymbolAddress((void**)&Hhi, g_Hhi);
    cudaGetSymbolAddress((void**)&Hlo, g_Hlo);
    cudaGetSymbolAddress((void**)&W1h, g_W1h);
    cudaGetSymbolAddress((void**)&W2h, g_W2h);
    cudaGetSymbolAddress((void**)&Part, g_Part);

    // launch order: GEMM1 is the 6th launch (ncu -s 5 -c 1 captures it)
    gating_kernel<<<NN, 128>>>(x, Wg);                                   // 1
    assign_kernel<<<1, 256>>>();                                         // 2
    dispatch_kernel<<<SLOTS, 256>>>(x);                                  // 3
    wconv_kernel<<<2048, 256>>>(W1, W1h, EE * DFF * DD / 2);             // 4
    wconv_kernel<<<2048, 256>>>(W2, W2h, EE * DD * DFF / 2);             // 5

    // GEMM1: H = relu(X @ W1^T); per expert M=cnt, N=DFF, K=DD; fused relu+fp16-split
    {
        dim3 grid(DFF / 256, CAP / 128, EE);                             // 6 (profiled)
        gemm_tc_kernel<true><<<grid, 512, GEMM_SMEM_BYTES>>>(
            Xhi, Xlo, W1h, nullptr, Hhi, Hlo,
            DFF, DD, DD, 1, 0,
            CAP * DD / 2, DFF * DD / 2, 0);
    }

    // GEMM2: Part[s] = H[:, s*1024:(s+1)*1024] @ W2[:, slice]^T (split-K x4)
    {
        dim3 grid(DD / 256, CAP / 128, EE * NSPLIT2);                    // 7
        gemm_tc_kernel<false><<<grid, 512, GEMM_SMEM_BYTES>>>(
            Hhi, Hlo, W2h, Part, nullptr, nullptr,
            DD, DFF, DFF / NSPLIT2, NSPLIT2, (long long)EE * CAP * DD,
            CAP * DFF / 2, DD * DFF / 2, CAP * DD);
    }

    combine_kernel<<<NN, 256>>>(y);                                      // 8
    aux_kernel<<<1, 1>>>(y, out_size);                                   // 9
}

// round 11
// speedup vs baseline: 4.7630x; 1.4488x over previous
#include <cuda_runtime.h>
#include <cuda_fp16.h>
#include <stdint.h>
#include <math.h>

// Problem constants
#define BB   4
#define SS   2048
#define DD   1024
#define DFF  4096
#define EE   8
#define NN   (BB*SS)          // 8192 tokens
#define KTOP 2
#define SLOTS (NN*KTOP)       // 16384
#define CAP  1280
#define EPS_F 1e-9f
#define NSPLIT2 4             // split-K factor for GEMM2

// ---------------- device scratch ----------------
__device__ float    g_Part[NSPLIT2 * EE * CAP * DD];  // GEMM2 split-K partials
__device__ unsigned g_Xh[EE * CAP * DD / 2];      // dispatched X, fp16x2
__device__ unsigned g_Hh[EE * CAP * DFF / 2];     // hidden, fp16x2
__device__ unsigned g_W1h[EE * DFF * DD / 2];     // W1 as fp16x2
__device__ unsigned g_W2h[EE * DD * DFF / 2];     // W2 as fp16x2
__device__ int   g_slot_expert[SLOTS];
__device__ int   g_slot_pos[SLOTS];
__device__ float g_slot_p[SLOTS];
__device__ float g_slot_w[SLOTS];
__device__ int   g_cnt[EE];
__device__ float g_imp[EE];

// ---------------- helpers ----------------
__device__ __forceinline__ unsigned packh(__half a, __half b)
{
    return ((unsigned)__half_as_ushort(b) << 16) | (unsigned)__half_as_ushort(a);
}

__device__ __forceinline__ void mma16816h(float c[4], const uint32_t a[4], const uint32_t b[2])
{
    asm volatile(
        "mma.sync.aligned.m16n8k16.row.col.f32.f16.f16.f32 "
        "{%0,%1,%2,%3},{%4,%5,%6,%7},{%8,%9},{%0,%1,%2,%3};\n"
        : "+f"(c[0]), "+f"(c[1]), "+f"(c[2]), "+f"(c[3])
        : "r"(a[0]), "r"(a[1]), "r"(a[2]), "r"(a[3]), "r"(b[0]), "r"(b[1]));
}

__device__ __forceinline__ void ldsm4(uint32_t r[4], uint32_t saddr)
{
    asm volatile("ldmatrix.sync.aligned.m8n8.x4.shared.b16 {%0,%1,%2,%3}, [%4];"
                 : "=r"(r[0]), "=r"(r[1]), "=r"(r[2]), "=r"(r[3]) : "r"(saddr));
}

__device__ __forceinline__ void cpa16(uint32_t saddr, const void* g)
{
    asm volatile("cp.async.cg.shared.global [%0], [%1], 16;\n" :: "r"(saddr), "l"(g));
}
__device__ __forceinline__ void cpa_commit() { asm volatile("cp.async.commit_group;\n"); }

__device__ __forceinline__ uint32_t smem_u32(const void* p) {
    uint32_t a;
    asm("{ .reg .u64 t; cvta.to.shared.u64 t, %1; cvt.u32.u64 %0, t; }" : "=r"(a) : "l"(p));
    return a;
}

// ---------------- 1) gating ----------------
__global__ void gating_kernel(const float* __restrict__ x, const float* __restrict__ Wg)
{
    int t = blockIdx.x;
    int tid = threadIdx.x;                  // 128 threads
    const float4* xv = (const float4*)(x + (size_t)t * DD);

    float acc[EE];
#pragma unroll
    for (int e = 0; e < EE; e++) acc[e] = 0.f;

    for (int i = tid; i < DD / 4; i += 128) {
        float4 xx = xv[i];
#pragma unroll
        for (int e = 0; e < EE; e++) {
            float4 wv = *(const float4*)(Wg + (size_t)e * DD + i * 4);
            acc[e] += xx.x * wv.x + xx.y * wv.y + xx.z * wv.z + xx.w * wv.w;
        }
    }

    __shared__ float sh[EE][128];
#pragma unroll
    for (int e = 0; e < EE; e++) sh[e][tid] = acc[e];
    __syncthreads();
    for (int s = 64; s > 0; s >>= 1) {
        if (tid < s) {
#pragma unroll
            for (int e = 0; e < EE; e++) sh[e][tid] += sh[e][tid + s];
        }
        __syncthreads();
    }

    if (tid == 0) {
        float v[EE];
#pragma unroll
        for (int e = 0; e < EE; e++) v[e] = sh[e][0];
        int i0 = 0; float s0 = v[0];
#pragma unroll
        for (int e = 1; e < EE; e++) if (v[e] > s0) { s0 = v[e]; i0 = e; }
        int i1 = -1; float s1 = -INFINITY;
#pragma unroll
        for (int e = 0; e < EE; e++) if (e != i0 && v[e] > s1) { s1 = v[e]; i1 = e; }
        float e1 = expf(s1 - s0);
        float denom = 1.f + e1;
        g_slot_expert[2 * t + 0] = i0;
        g_slot_expert[2 * t + 1] = i1;
        g_slot_p[2 * t + 0] = 1.f / denom;
        g_slot_p[2 * t + 1] = e1 / denom;
    }
}

// ---------------- 2) ordered capacity assignment ----------------
__global__ void assign_kernel()
{
    const int T = 256;
    const int CH = SLOTS / T;
    int tid = threadIdx.x;
    int base = tid * CH;

    __shared__ int   scnt[T][EE];
    __shared__ float simp[T][EE];

    int lc[EE];
#pragma unroll
    for (int e = 0; e < EE; e++) lc[e] = 0;
    for (int i = 0; i < CH; i++) lc[g_slot_expert[base + i]]++;
#pragma unroll
    for (int e = 0; e < EE; e++) scnt[tid][e] = lc[e];
    __syncthreads();

    if (tid < EE) {
        int e = tid, run = 0;
        for (int t2 = 0; t2 < T; t2++) { int c = scnt[t2][e]; scnt[t2][e] = run; run += c; }
        g_cnt[e] = min(run, CAP);
    }
    __syncthreads();

    int off[EE];
    float impl[EE];
#pragma unroll
    for (int e = 0; e < EE; e++) { off[e] = scnt[tid][e]; impl[e] = 0.f; }

    for (int i = 0; i < CH; i += 2) {
        int sA = base + i, sBs = base + i + 1;
        int e0 = g_slot_expert[sA], e1 = g_slot_expert[sBs];
        int p0 = off[e0]++;
        int p1 = off[e1]++;
        bool k0 = p0 < CAP, k1 = p1 < CAP;
        float w0 = k0 ? g_slot_p[sA] : 0.f;
        float w1 = k1 ? g_slot_p[sBs] : 0.f;
        float s = w0 + w1 + EPS_F;
        w0 /= s; w1 /= s;
        bool v0 = w0 > 0.f, v1 = w1 > 0.f;
        g_slot_w[sA] = w0;
        g_slot_w[sBs] = w1;
        g_slot_pos[sA]  = v0 ? p0 : -1;
        g_slot_pos[sBs] = v1 ? p1 : -1;
        if (v0) impl[e0] += w0;
        if (v1) impl[e1] += w1;
    }
#pragma unroll
    for (int e = 0; e < EE; e++) simp[tid][e] = impl[e];
    __syncthreads();
    if (tid < EE) {
        int e = tid;
        float s = 0.f;
        for (int t2 = 0; t2 < T; t2++) s += simp[t2][e];
        g_imp[e] = s;
    }
}

// ---------------- 3) dispatch: X -> fp16 ----------------
__global__ void dispatch_kernel(const float* __restrict__ x)
{
    int slot = blockIdx.x;
    int pos = g_slot_pos[slot];
    if (pos < 0) return;
    int e = g_slot_expert[slot];
    float w = g_slot_w[slot];
    int tok = slot >> 1;
    const float4* xs = (const float4*)(x + (size_t)tok * DD);
    size_t rowbase = ((size_t)(e * CAP + pos)) * (DD / 2);
    int i = threadIdx.x;                    // 256 threads
    float4 v = xs[i];
    g_Xh[rowbase + 2 * i + 0] = packh(__float2half_rn(v.x * w), __float2half_rn(v.y * w));
    g_Xh[rowbase + 2 * i + 1] = packh(__float2half_rn(v.z * w), __float2half_rn(v.w * w));
}

// ---------------- weight convert: fp32 -> fp16 ----------------
__global__ void wconv_kernel(const float* __restrict__ W, unsigned* __restrict__ hi, int n2)
{
    int i = blockIdx.x * blockDim.x + threadIdx.x;
    int stride = gridDim.x * blockDim.x;
    for (; i < n2; i += stride) {
        float2 v = ((const float2*)W)[i];
        hi[i] = packh(__float2half_rn(v.x), __float2half_rn(v.y));
    }
}

// ---------------- ldmatrix + mma.sync NT GEMM (single fp16 product) ----------------
// C[m,n] = sum_k A[m,k]*B[n,k].  CTA tile 128x256x32, 16 warps (2x8), warp 64x32.
// 3-stage cp.async ring, one __syncthreads per chunk. Optional split-K.
#define PITCH 20                   // u32 per 32-fp16 row (16 data + 4 pad); LDSM conflict-free
#define A_U32 (128 * PITCH)        // A per stage: 2560 u32 (10 KB)
#define B_U32 (256 * PITCH)        // B per stage: 5120 u32 (20 KB)
#define STAGE_U32 (A_U32 + B_U32)  // 7680 u32 (30 KB)
#define NSTAGE 3
#define GEMM_SMEM_BYTES (NSTAGE * STAGE_U32 * 4)   // 92160 B
static_assert(GEMM_SMEM_BYTES <= 227 * 1024, "smem");

template<bool FUSE_RELU_H>
__global__ __launch_bounds__(512, 1)
void gemm_tc_kernel(const unsigned* __restrict__ Ah, const unsigned* __restrict__ Bh,
                    float* __restrict__ Cf, unsigned* __restrict__ Ch,
                    int Nn, int Kfull, int Klen, int nsplit, long long partStride,
                    int strideA2, int strideB2, int strideC)
{
    extern __shared__ unsigned smem[];

    int zs = blockIdx.z;
    int e  = zs / nsplit;
    int sp = zs - e * nsplit;
    int M = g_cnt[e];
    int m0 = blockIdx.y * 128;
    if (m0 >= M) return;
    int n0 = blockIdx.x * 256;
    int K2 = Kfull >> 1;
    int k0_2 = sp * (Klen >> 1);

    const unsigned* Ap = Ah + (size_t)e * strideA2 + k0_2;
    const unsigned* Bp = Bh + (size_t)e * strideB2 + k0_2;

    int tid = threadIdx.x;
    int lane = tid & 31, warp = tid >> 5;
    int wm = warp >> 3, wn = warp & 7;      // 2 x 8 warps, warp tile 64x32

    uint32_t sbase = smem_u32(smem);

    // loader mapping: 4 threads/row; thread covers u32 [c0, c0+4)
    int lrow = tid >> 2;                    // 0..127
    int c0 = (tid & 3) * 4;
    int gm = m0 + lrow;
    int gmc = min(gm, M - 1);

    // LDSM per-lane geometry
    int aRow  = wm * 64 + (lane & 15);            // + mi*16
    int aHalf = lane >> 4;                        // k-half 0/1
    int bRow  = wn * 32 + (lane & 7) + ((lane >> 4) << 3);  // + ni2*16
    int bHalf = (lane >> 3) & 1;

    float acc[4][4][4];
#pragma unroll
    for (int mi = 0; mi < 4; mi++)
#pragma unroll
        for (int ni = 0; ni < 4; ni++)
#pragma unroll
            for (int q = 0; q < 4; q++) acc[mi][ni][q] = 0.f;

    int nch = Klen / 32;

    auto issue = [&](int it) {
        uint32_t soff = (uint32_t)(it % NSTAGE) * STAGE_U32;
        int kt2 = it * 16;
        // A: 128 rows x 16 u32 = 512 threads x 4 u32, exact cover
        {
            uint32_t dst = sbase + (uint32_t)(soff + lrow * PITCH + c0) * 4;
            cpa16(dst, Ap + (size_t)gmc * K2 + kt2 + c0);
        }
        // B: 256 rows x 16 u32, 2 chunks per thread
#pragma unroll
        for (int j = 0; j < 2; j++) {
            int idx = tid + j * 512;
            int r = idx >> 2;
            int cc = (idx & 3) * 4;
            uint32_t dst = sbase + (uint32_t)(soff + A_U32 + r * PITCH + cc) * 4;
            cpa16(dst, Bp + (size_t)(n0 + r) * K2 + kt2 + cc);
        }
        cpa_commit();
    };

    issue(0);
    issue(1);

    for (int it = 0; it < nch; it++) {
        if (it + 1 < nch) asm volatile("cp.async.wait_group 1;\n" ::: "memory");
        else              asm volatile("cp.async.wait_group 0;\n" ::: "memory");
        __syncthreads();   // stage it ready; stage (it-1)%3 free for refill

        if (it + 2 < nch) issue(it + 2);

        uint32_t sA = sbase + (uint32_t)((it % NSTAGE) * STAGE_U32) * 4;
        uint32_t sB = sA + A_U32 * 4;

#pragma unroll
        for (int ks = 0; ks < 2; ks++) {
            int kb = ks * 8;
            uint32_t bh[2][4];
#pragma unroll
            for (int n2 = 0; n2 < 2; n2++) {
                uint32_t ao = (uint32_t)((bRow + n2 * 16) * PITCH + kb + bHalf * 4) * 4;
                ldsm4(bh[n2], sB + ao);
            }
#pragma unroll
            for (int mi = 0; mi < 4; mi++) {
                uint32_t ah[4];
                uint32_t ao = (uint32_t)((aRow + mi * 16) * PITCH + kb + aHalf * 4) * 4;
                ldsm4(ah, sA + ao);
#pragma unroll
                for (int ni = 0; ni < 4; ni++) {
                    mma16816h(acc[mi][ni], ah, &bh[ni >> 1][(ni & 1) * 2]);
                }
            }
        }
    }

    // --- epilogue ---
#pragma unroll
    for (int mi = 0; mi < 4; mi++) {
#pragma unroll
        for (int ni = 0; ni < 4; ni++) {
            int r0 = m0 + wm * 64 + mi * 16 + (lane >> 2);
            int cc = n0 + wn * 32 + ni * 8 + 2 * (lane & 3);
            float* a = acc[mi][ni];
            if (FUSE_RELU_H) {
                size_t eoff = (size_t)e * ((size_t)CAP * (Nn >> 1));
                if (r0 < M) {
                    Ch[eoff + (size_t)r0 * (Nn >> 1) + (cc >> 1)] =
                        packh(__float2half_rn(fmaxf(a[0], 0.f)), __float2half_rn(fmaxf(a[1], 0.f)));
                }
                if (r0 + 8 < M) {
                    Ch[eoff + (size_t)(r0 + 8) * (Nn >> 1) + (cc >> 1)] =
                        packh(__float2half_rn(fmaxf(a[2], 0.f)), __float2half_rn(fmaxf(a[3], 0.f)));
                }
            } else {
                float* Cp = Cf + (long long)sp * partStride + (size_t)e * strideC;
                if (r0 < M)
                    *(float2*)(Cp + (size_t)r0 * Nn + cc) = make_float2(a[0], a[1]);
                if (r0 + 8 < M)
                    *(float2*)(Cp + (size_t)(r0 + 8) * Nn + cc) = make_float2(a[2], a[3]);
            }
        }
    }
}

// ---------------- 6) combine: sum split-K partials over kept slots ----------------
__global__ void combine_kernel(float* __restrict__ y)
{
    int t = blockIdx.x;
    int i = threadIdx.x;
    const long long PS = (long long)EE * CAP * DD;
    float4 acc = make_float4(0.f, 0.f, 0.f, 0.f);
#pragma unroll
    for (int j = 0; j < KTOP; j++) {
        int slot = t * KTOP + j;
        int pos = g_slot_pos[slot];
        if (pos >= 0) {
            int e = g_slot_expert[slot];
            size_t rb = ((size_t)(e * CAP + pos)) * DD;
#pragma unroll
            for (int s = 0; s < NSPLIT2; s++) {
                const float4* o = (const float4*)(g_Part + s * PS + rb);
                float4 v = o[i];
                acc.x += v.x; acc.y += v.y; acc.z += v.z; acc.w += v.w;
            }
        }
    }
    ((float4*)(y + (size_t)t * DD))[i] = acc;
}

// ---------------- 7) aux loss ----------------
__global__ void aux_kernel(float* __restrict__ out, int out_size)
{
    float tc = 0.f, ic = 0.f;
#pragma unroll
    for (int e = 0; e < EE; e++) { tc += (float)g_cnt[e]; ic += g_imp[e]; }
    float aux = 0.f;
#pragma unroll
    for (int e = 0; e < EE; e++) aux += ((float)g_cnt[e] / tc) * (g_imp[e] / ic);
    out[out_size - 1] = aux * (float)EE;
}

// ---------------- launch ----------------
extern "C" void kernel_launch(void* const* d_in, const int* in_sizes, int n_in,
                              void* d_out, int out_size)
{
    const float* x  = (const float*)d_in[0];
    const float* Wg = (const float*)d_in[1];
    const float* W1 = (const float*)d_in[2];
    const float* W2 = (const float*)d_in[3];
    float* y = (float*)d_out;
    (void)in_sizes; (void)n_in;

    cudaFuncSetAttribute(gemm_tc_kernel<true>,  cudaFuncAttributeMaxDynamicSharedMemorySize, GEMM_SMEM_BYTES);
    cudaFuncSetAttribute(gemm_tc_kernel<false>, cudaFuncAttributeMaxDynamicSharedMemorySize, GEMM_SMEM_BYTES);

    unsigned *Xh, *Hh, *W1h, *W2h;
    float *Part;
    cudaGetSymbolAddress((void**)&Xh,  g_Xh);
    cudaGetSymbolAddress((void**)&Hh,  g_Hh);
    cudaGetSymbolAddress((void**)&W1h, g_W1h);
    cudaGetSymbolAddress((void**)&W2h, g_W2h);
    cudaGetSymbolAddress((void**)&Part, g_Part);

    // launch order: GEMM1 is the 6th launch (ncu -s 5 -c 1 captures it)
    gating_kernel<<<NN, 128>>>(x, Wg);                                   // 1
    assign_kernel<<<1, 256>>>();                                         // 2
    dispatch_kernel<<<SLOTS, 256>>>(x);                                  // 3
    wconv_kernel<<<2048, 256>>>(W1, W1h, EE * DFF * DD / 2);             // 4
    wconv_kernel<<<2048, 256>>>(W2, W2h, EE * DD * DFF / 2);             // 5

    // GEMM1: H = relu(X @ W1^T); per expert M=cnt, N=DFF, K=DD; fused relu+fp16 store
    {
        dim3 grid(DFF / 256, CAP / 128, EE);                             // 6 (profiled)
        gemm_tc_kernel<true><<<grid, 512, GEMM_SMEM_BYTES>>>(
            Xh, W1h, nullptr, Hh,
            DFF, DD, DD, 1, 0,
            CAP * DD / 2, DFF * DD / 2, 0);
    }

    // GEMM2: Part[s] = H[:, s*1024:(s+1)*1024] @ W2[:, slice]^T (split-K x4)
    {
        dim3 grid(DD / 256, CAP / 128, EE * NSPLIT2);                    // 7
        gemm_tc_kernel<false><<<grid, 512, GEMM_SMEM_BYTES>>>(
            Hh, W2h, Part, nullptr,
            DD, DFF, DFF / NSPLIT2, NSPLIT2, (long long)EE * CAP * DD,
            CAP * DFF / 2, DD * DFF / 2, CAP * DD);
    }

    combine_kernel<<<NN, 256>>>(y);                                      // 8
    aux_kernel<<<1, 1>>>(y, out_size);                                   // 9
}

// round 13
// speedup vs baseline: 5.1517x; 1.0816x over previous
#include <cuda_runtime.h>
#include <cuda_fp16.h>
#include <stdint.h>
#include <math.h>

// Problem constants
#define BB   4
#define SS   2048
#define DD   1024
#define DFF  4096
#define EE   8
#define NN   (BB*SS)          // 8192 tokens
#define KTOP 2
#define SLOTS (NN*KTOP)       // 16384
#define CAP  1280
#define EPS_F 1e-9f
#define NSPLIT2 4             // split-K factor for GEMM2

// ---------------- device scratch ----------------
__device__ float    g_Part[NSPLIT2 * EE * CAP * DD];  // GEMM2 split-K partials
__device__ unsigned g_Xh[EE * CAP * DD / 2];      // dispatched X, fp16x2
__device__ unsigned g_Hh[EE * CAP * DFF / 2];     // hidden, fp16x2
__device__ unsigned g_W1h[EE * DFF * DD / 2];     // W1 as fp16x2
__device__ unsigned g_W2h[EE * DD * DFF / 2];     // W2 as fp16x2
__device__ int   g_slot_expert[SLOTS];
__device__ int   g_slot_pos[SLOTS];
__device__ float g_slot_p[SLOTS];
__device__ float g_slot_w[SLOTS];
__device__ int   g_cnt[EE];
__device__ float g_imp[EE];

// ---------------- helpers ----------------
__device__ __forceinline__ unsigned packh(__half a, __half b)
{
    return ((unsigned)__half_as_ushort(b) << 16) | (unsigned)__half_as_ushort(a);
}

__device__ __forceinline__ void mma16816h(float c[4], const uint32_t a[4], const uint32_t b[2])
{
    asm volatile(
        "mma.sync.aligned.m16n8k16.row.col.f32.f16.f16.f32 "
        "{%0,%1,%2,%3},{%4,%5,%6,%7},{%8,%9},{%0,%1,%2,%3};\n"
        : "+f"(c[0]), "+f"(c[1]), "+f"(c[2]), "+f"(c[3])
        : "r"(a[0]), "r"(a[1]), "r"(a[2]), "r"(a[3]), "r"(b[0]), "r"(b[1]));
}

__device__ __forceinline__ void ldsm4(uint32_t r[4], uint32_t saddr)
{
    asm volatile("ldmatrix.sync.aligned.m8n8.x4.shared.b16 {%0,%1,%2,%3}, [%4];"
                 : "=r"(r[0]), "=r"(r[1]), "=r"(r[2]), "=r"(r[3]) : "r"(saddr));
}

__device__ __forceinline__ void cpa16(uint32_t saddr, const void* g)
{
    asm volatile("cp.async.cg.shared.global [%0], [%1], 16;\n" :: "r"(saddr), "l"(g));
}
__device__ __forceinline__ void cpa_commit() { asm volatile("cp.async.commit_group;\n"); }

__device__ __forceinline__ uint32_t smem_u32(const void* p) {
    uint32_t a;
    asm("{ .reg .u64 t; cvta.to.shared.u64 t, %1; cvt.u32.u64 %0, t; }" : "=r"(a) : "l"(p));
    return a;
}

// ---------------- 1) gating + fused weight conversion ----------------
__global__ void gating_kernel(const float* __restrict__ x, const float* __restrict__ Wg,
                              const float* __restrict__ W1, const float* __restrict__ W2)
{
    int t = blockIdx.x;
    int tid = threadIdx.x;                  // 128 threads
    const float4* xv = (const float4*)(x + (size_t)t * DD);

    float acc[EE];
#pragma unroll
    for (int e = 0; e < EE; e++) acc[e] = 0.f;

    for (int i = tid; i < DD / 4; i += 128) {
        float4 xx = xv[i];
#pragma unroll
        for (int e = 0; e < EE; e++) {
            float4 wv = *(const float4*)(Wg + (size_t)e * DD + i * 4);
            acc[e] += xx.x * wv.x + xx.y * wv.y + xx.z * wv.z + xx.w * wv.w;
        }
    }

    __shared__ float sh[EE][128];
#pragma unroll
    for (int e = 0; e < EE; e++) sh[e][tid] = acc[e];
    __syncthreads();
    for (int s = 64; s > 0; s >>= 1) {
        if (tid < s) {
#pragma unroll
            for (int e = 0; e < EE; e++) sh[e][tid] += sh[e][tid + s];
        }
        __syncthreads();
    }

    if (tid == 0) {
        float v[EE];
#pragma unroll
        for (int e = 0; e < EE; e++) v[e] = sh[e][0];
        int i0 = 0; float s0 = v[0];
#pragma unroll
        for (int e = 1; e < EE; e++) if (v[e] > s0) { s0 = v[e]; i0 = e; }
        int i1 = -1; float s1 = -INFINITY;
#pragma unroll
        for (int e = 0; e < EE; e++) if (e != i0 && v[e] > s1) { s1 = v[e]; i1 = e; }
        float e1 = expf(s1 - s0);
        float denom = 1.f + e1;
        g_slot_expert[2 * t + 0] = i0;
        g_slot_expert[2 * t + 1] = i1;
        g_slot_p[2 * t + 0] = 1.f / denom;
        g_slot_p[2 * t + 1] = e1 / denom;
    }

    // --- fused weight conversion (grid-stride over both weight tensors) ---
    {
        const int n2 = EE * DFF * DD / 2;       // u32-pair count per tensor
        int i = blockIdx.x * blockDim.x + tid - tid; // placate compiler (kept simple below)
        int gidx = blockIdx.x * 128 + tid;
        int gstride = gridDim.x * 128;
        for (int j = gidx; j < n2; j += gstride) {
            float2 v1 = ((const float2*)W1)[j];
            g_W1h[j] = packh(__float2half_rn(v1.x), __float2half_rn(v1.y));
            float2 v2 = ((const float2*)W2)[j];
            g_W2h[j] = packh(__float2half_rn(v2.x), __float2half_rn(v2.y));
        }
        (void)i;
    }
}

// ---------------- 2) ordered capacity assignment ----------------
__global__ void assign_kernel()
{
    const int T = 256;
    const int CH = SLOTS / T;
    int tid = threadIdx.x;
    int base = tid * CH;

    __shared__ int   scnt[T][EE];
    __shared__ float simp[T][EE];

    int lc[EE];
#pragma unroll
    for (int e = 0; e < EE; e++) lc[e] = 0;
    for (int i = 0; i < CH; i++) lc[g_slot_expert[base + i]]++;
#pragma unroll
    for (int e = 0; e < EE; e++) scnt[tid][e] = lc[e];
    __syncthreads();

    if (tid < EE) {
        int e = tid, run = 0;
        for (int t2 = 0; t2 < T; t2++) { int c = scnt[t2][e]; scnt[t2][e] = run; run += c; }
        g_cnt[e] = min(run, CAP);
    }
    __syncthreads();

    int off[EE];
    float impl[EE];
#pragma unroll
    for (int e = 0; e < EE; e++) { off[e] = scnt[tid][e]; impl[e] = 0.f; }

    for (int i = 0; i < CH; i += 2) {
        int sA = base + i, sBs = base + i + 1;
        int e0 = g_slot_expert[sA], e1 = g_slot_expert[sBs];
        int p0 = off[e0]++;
        int p1 = off[e1]++;
        bool k0 = p0 < CAP, k1 = p1 < CAP;
        float w0 = k0 ? g_slot_p[sA] : 0.f;
        float w1 = k1 ? g_slot_p[sBs] : 0.f;
        float s = w0 + w1 + EPS_F;
        w0 /= s; w1 /= s;
        bool v0 = w0 > 0.f, v1 = w1 > 0.f;
        g_slot_w[sA] = w0;
        g_slot_w[sBs] = w1;
        g_slot_pos[sA]  = v0 ? p0 : -1;
        g_slot_pos[sBs] = v1 ? p1 : -1;
        if (v0) impl[e0] += w0;
        if (v1) impl[e1] += w1;
    }
#pragma unroll
    for (int e = 0; e < EE; e++) simp[tid][e] = impl[e];
    __syncthreads();
    if (tid < EE) {
        int e = tid;
        float s = 0.f;
        for (int t2 = 0; t2 < T; t2++) s += simp[t2][e];
        g_imp[e] = s;
    }
}

// ---------------- 3) dispatch: X -> fp16 ----------------
__global__ void dispatch_kernel(const float* __restrict__ x)
{
    int slot = blockIdx.x;
    int pos = g_slot_pos[slot];
    if (pos < 0) return;
    int e = g_slot_expert[slot];
    float w = g_slot_w[slot];
    int tok = slot >> 1;
    const float4* xs = (const float4*)(x + (size_t)tok * DD);
    size_t rowbase = ((size_t)(e * CAP + pos)) * (DD / 2);
    int i = threadIdx.x;                    // 256 threads
    float4 v = xs[i];
    g_Xh[rowbase + 2 * i + 0] = packh(__float2half_rn(v.x * w), __float2half_rn(v.y * w));
    g_Xh[rowbase + 2 * i + 1] = packh(__float2half_rn(v.z * w), __float2half_rn(v.w * w));
}

// ---------------- ldmatrix + mma.sync NT GEMM (single fp16 product) ----------------
// C[m,n] = sum_k A[m,k]*B[n,k].  CTA tile 128x256x64, 16 warps (2x8), warp 64x32.
// 3-stage cp.async ring, one __syncthreads per 64-K chunk. Optional split-K.
#define PITCH 36                   // u32 per 64-fp16 row (32 data + 4 pad); LDSM conflict-free
#define A_U32 (128 * PITCH)        // A per stage: 4608 u32 (18 KB)
#define B_U32 (256 * PITCH)        // B per stage: 9216 u32 (36 KB)
#define STAGE_U32 (A_U32 + B_U32)  // 13824 u32 (54 KB)
#define NSTAGE 3
#define GEMM_SMEM_BYTES (NSTAGE * STAGE_U32 * 4)   // 165888 B
static_assert(GEMM_SMEM_BYTES <= 227 * 1024, "smem");

template<bool FUSE_RELU_H>
__global__ __launch_bounds__(512, 1)
void gemm_tc_kernel(const unsigned* __restrict__ Ah, const unsigned* __restrict__ Bh,
                    float* __restrict__ Cf, unsigned* __restrict__ Ch,
                    int Nn, int Kfull, int Klen, int nsplit, long long partStride,
                    int strideA2, int strideB2, int strideC)
{
    extern __shared__ unsigned smem[];

    int zs = blockIdx.z;
    int e  = zs / nsplit;
    int sp = zs - e * nsplit;
    int M = g_cnt[e];
    int m0 = blockIdx.y * 128;
    if (m0 >= M) return;
    int n0 = blockIdx.x * 256;
    int K2 = Kfull >> 1;
    int k0_2 = sp * (Klen >> 1);

    const unsigned* Ap = Ah + (size_t)e * strideA2 + k0_2;
    const unsigned* Bp = Bh + (size_t)e * strideB2 + k0_2;

    int tid = threadIdx.x;
    int lane = tid & 31, warp = tid >> 5;
    int wm = warp >> 3, wn = warp & 7;      // 2 x 8 warps, warp tile 64x32

    uint32_t sbase = smem_u32(smem);

    // loader mapping: 4 threads/row; thread covers u32 [c0, c0+8)
    int lrow = tid >> 2;                    // 0..127
    int c0 = (tid & 3) * 8;
    int gm = m0 + lrow;
    int gmc = min(gm, M - 1);

    // LDSM per-lane geometry
    int aRow  = wm * 64 + (lane & 15);            // + mi*16
    int aHalf = lane >> 4;                        // k-half 0/1
    int bRow  = wn * 32 + (lane & 7) + ((lane >> 4) << 3);  // + ni2*16
    int bHalf = (lane >> 3) & 1;

    float acc[4][4][4];
#pragma unroll
    for (int mi = 0; mi < 4; mi++)
#pragma unroll
        for (int ni = 0; ni < 4; ni++)
#pragma unroll
            for (int q = 0; q < 4; q++) acc[mi][ni][q] = 0.f;

    int nch = Klen / 64;

    auto issue = [&](int it) {
        uint32_t soff = (uint32_t)(it % NSTAGE) * STAGE_U32;
        int kt2 = it * 32;
        // A: 128 rows x 32 u32 = 512 threads x 8 u32 (two cpa16)
        {
            uint32_t dst = sbase + (uint32_t)(soff + lrow * PITCH + c0) * 4;
            size_t ga = (size_t)gmc * K2 + kt2 + c0;
            cpa16(dst,      Ap + ga);
            cpa16(dst + 16, Ap + ga + 4);
        }
        // B: 256 rows x 32 u32, 2 row-segments per thread (four cpa16)
#pragma unroll
        for (int j = 0; j < 2; j++) {
            int idx = tid + j * 512;
            int r = idx >> 2;
            int cc = (idx & 3) * 8;
            uint32_t dst = sbase + (uint32_t)(soff + A_U32 + r * PITCH + cc) * 4;
            size_t gb = (size_t)(n0 + r) * K2 + kt2 + cc;
            cpa16(dst,      Bp + gb);
            cpa16(dst + 16, Bp + gb + 4);
        }
        cpa_commit();
    };

    issue(0);
    issue(1);

    for (int it = 0; it < nch; it++) {
        if (it + 1 < nch) asm volatile("cp.async.wait_group 1;\n" ::: "memory");
        else              asm volatile("cp.async.wait_group 0;\n" ::: "memory");
        __syncthreads();   // stage it ready; stage (it-1)%3 free for refill

        if (it + 2 < nch) issue(it + 2);

        uint32_t sA = sbase + (uint32_t)((it % NSTAGE) * STAGE_U32) * 4;
        uint32_t sB = sA + A_U32 * 4;

#pragma unroll
        for (int ks = 0; ks < 4; ks++) {
            int kb = ks * 8;
            uint32_t bh[2][4];
#pragma unroll
            for (int n2 = 0; n2 < 2; n2++) {
                uint32_t ao = (uint32_t)((bRow + n2 * 16) * PITCH + kb + bHalf * 4) * 4;
                ldsm4(bh[n2], sB + ao);
            }
#pragma unroll
            for (int mi = 0; mi < 4; mi++) {
                uint32_t ah[4];
                uint32_t ao = (uint32_t)((aRow + mi * 16) * PITCH + kb + aHalf * 4) * 4;
                ldsm4(ah, sA + ao);
#pragma unroll
                for (int ni = 0; ni < 4; ni++) {
                    mma16816h(acc[mi][ni], ah, &bh[ni >> 1][(ni & 1) * 2]);
                }
            }
        }
    }

    // --- epilogue ---
#pragma unroll
    for (int mi = 0; mi < 4; mi++) {
#pragma unroll
        for (int ni = 0; ni < 4; ni++) {
            int r0 = m0 + wm * 64 + mi * 16 + (lane >> 2);
            int cc = n0 + wn * 32 + ni * 8 + 2 * (lane & 3);
            float* a = acc[mi][ni];
            if (FUSE_RELU_H) {
                size_t eoff = (size_t)e * ((size_t)CAP * (Nn >> 1));
                if (r0 < M) {
                    Ch[eoff + (size_t)r0 * (Nn >> 1) + (cc >> 1)] =
                        packh(__float2half_rn(fmaxf(a[0], 0.f)), __float2half_rn(fmaxf(a[1], 0.f)));
                }
                if (r0 + 8 < M) {
                    Ch[eoff + (size_t)(r0 + 8) * (Nn >> 1) + (cc >> 1)] =
                        packh(__float2half_rn(fmaxf(a[2], 0.f)), __float2half_rn(fmaxf(a[3], 0.f)));
                }
            } else {
                float* Cp = Cf + (long long)sp * partStride + (size_t)e * strideC;
                if (r0 < M)
                    *(float2*)(Cp + (size_t)r0 * Nn + cc) = make_float2(a[0], a[1]);
                if (r0 + 8 < M)
                    *(float2*)(Cp + (size_t)(r0 + 8) * Nn + cc) = make_float2(a[2], a[3]);
            }
        }
    }
}

// ---------------- 6) combine: sum split-K partials over kept slots ----------------
__global__ void combine_kernel(float* __restrict__ y)
{
    int t = blockIdx.x;
    int i = threadIdx.x;
    const long long PS = (long long)EE * CAP * DD;
    float4 acc = make_float4(0.f, 0.f, 0.f, 0.f);
#pragma unroll
    for (int j = 0; j < KTOP; j++) {
        int slot = t * KTOP + j;
        int pos = g_slot_pos[slot];
        if (pos >= 0) {
            int e = g_slot_expert[slot];
            size_t rb = ((size_t)(e * CAP + pos)) * DD;
#pragma unroll
            for (int s = 0; s < NSPLIT2; s++) {
                const float4* o = (const float4*)(g_Part + s * PS + rb);
                float4 v = o[i];
                acc.x += v.x; acc.y += v.y; acc.z += v.z; acc.w += v.w;
            }
        }
    }
    ((float4*)(y + (size_t)t * DD))[i] = acc;
}

// ---------------- 7) aux loss ----------------
__global__ void aux_kernel(float* __restrict__ out, int out_size)
{
    float tc = 0.f, ic = 0.f;
#pragma unroll
    for (int e = 0; e < EE; e++) { tc += (float)g_cnt[e]; ic += g_imp[e]; }
    float aux = 0.f;
#pragma unroll
    for (int e = 0; e < EE; e++) aux += ((float)g_cnt[e] / tc) * (g_imp[e] / ic);
    out[out_size - 1] = aux * (float)EE;
}

// ---------------- launch ----------------
extern "C" void kernel_launch(void* const* d_in, const int* in_sizes, int n_in,
                              void* d_out, int out_size)
{
    const float* x  = (const float*)d_in[0];
    const float* Wg = (const float*)d_in[1];
    const float* W1 = (const float*)d_in[2];
    const float* W2 = (const float*)d_in[3];
    float* y = (float*)d_out;
    (void)in_sizes; (void)n_in;

    cudaFuncSetAttribute(gemm_tc_kernel<true>,  cudaFuncAttributeMaxDynamicSharedMemorySize, GEMM_SMEM_BYTES);
    cudaFuncSetAttribute(gemm_tc_kernel<false>, cudaFuncAttributeMaxDynamicSharedMemorySize, GEMM_SMEM_BYTES);

    unsigned *Xh, *Hh, *W1h, *W2h;
    float *Part;
    cudaGetSymbolAddress((void**)&Xh,  g_Xh);
    cudaGetSymbolAddress((void**)&Hh,  g_Hh);
    cudaGetSymbolAddress((void**)&W1h, g_W1h);
    cudaGetSymbolAddress((void**)&W2h, g_W2h);
    cudaGetSymbolAddress((void**)&Part, g_Part);

    // launch order: GEMM1 is the 4th kernel launch -> ncu captures it
    gating_kernel<<<NN, 128>>>(x, Wg, W1, W2);                           // 1 (+ fused wconv)
    assign_kernel<<<1, 256>>>();                                         // 2
    dispatch_kernel<<<SLOTS, 256>>>(x);                                  // 3

    // GEMM1: H = relu(X @ W1^T); per expert M=cnt, N=DFF, K=DD; fused relu+fp16 store
    {
        dim3 grid(DFF / 256, CAP / 128, EE);                             // 4 (profiled)
        gemm_tc_kernel<true><<<grid, 512, GEMM_SMEM_BYTES>>>(
            Xh, W1h, nullptr, Hh,
            DFF, DD, DD, 1, 0,
            CAP * DD / 2, DFF * DD / 2, 0);
    }

    // GEMM2: Part[s] = H[:, s*1024:(s+1)*1024] @ W2[:, slice]^T (split-K x4)
    {
        dim3 grid(DD / 256, CAP / 128, EE * NSPLIT2);                    // 5
        gemm_tc_kernel<false><<<grid, 512, GEMM_SMEM_BYTES>>>(
            Hh, W2h, Part, nullptr,
            DD, DFF, DFF / NSPLIT2, NSPLIT2, (long long)EE * CAP * DD,
            CAP * DFF / 2, DD * DFF / 2, CAP * DD);
    }

    combine_kernel<<<NN, 256>>>(y);                                      // 6
    aux_kernel<<<1, 1>>>(y, out_size);                                   // 7
}